// round 10
// baseline (speedup 1.0000x reference)
#include <cuda_runtime.h>
#include <math.h>
#include <stdint.h>

#define BB 256
#define HH 512
#define H4 2048
#define LEN 48
#define LOOKN 10
#define K2H 1024
#define STARTI 48
#define LABW 58
#define NBLK 296
#define NTHR 128
#define NSUB 8
#define SUBCNT 37
#define PAD 20

constexpr size_t O_WISEQ = 0;
constexpr size_t O_MID2  = O_WISEQ + (size_t)BB*LEN*HH;
constexpr size_t O_Y     = O_MID2  + (size_t)BB*LEN*HH;
constexpr size_t O_HT0   = O_Y     + (size_t)BB*LEN*HH;
constexpr size_t O_HT1   = O_HT0   + (size_t)BB*K2H;
constexpr size_t O_HE0   = O_HT1   + (size_t)BB*K2H;
constexpr size_t O_HE1   = O_HE0   + (size_t)BB*K2H;
constexpr size_t O_HM0   = O_HE1   + (size_t)BB*K2H;
constexpr size_t O_HM1   = O_HM0   + (size_t)BB*K2H;
constexpr size_t O_DECIN = O_HM1   + (size_t)BB*K2H;
constexpr size_t O_WTWHO = O_DECIN + (size_t)BB*HH;
constexpr size_t O_TU    = O_WTWHO + (size_t)BB*K2H;
constexpr size_t O_SC    = O_TU    + (size_t)BB*HH;
constexpr size_t O_XM    = O_SC    + (size_t)BB*HH;
constexpr size_t O_LAB   = O_XM    + (size_t)BB*HH;
constexpr size_t O_BSPI  = O_LAB   + 1024;
constexpr size_t O_BTGI  = O_BSPI  + H4;
constexpr size_t O_BMDI  = O_BTGI  + H4;
constexpr size_t O_WTGCI = O_BMDI  + H4;
constexpr size_t O_WI32  = O_WTGCI + H4;
constexpr size_t O_WE32  = O_WI32  + (size_t)512*512;
constexpr size_t O_VD32  = O_WE32  + (size_t)512*1024;
constexpr size_t O_WX32  = O_VD32  + (size_t)512*512;
constexpr size_t O_WTWH32= O_WX32  + (size_t)512*512;
constexpr size_t O_SPIH  = O_WTWH32+ (size_t)1024*1024;
constexpr size_t O_SPHH  = O_SPIH  + (size_t)H4*512;
constexpr size_t O_TGX   = O_SPHH  + (size_t)H4*512;
constexpr size_t O_TGHH  = O_TGX   + (size_t)H4*512;
constexpr size_t O_MDIH  = O_TGHH  + (size_t)H4*512;
constexpr size_t O_MDHH  = O_MDIH  + (size_t)H4*512;
constexpr size_t G_TOTAL = O_MDHH  + (size_t)H4*512;

__device__ float g_buf[G_TOTAL];
__device__ __align__(128) unsigned g_arr[NSUB * 32];
__device__ unsigned g_master;
__device__ unsigned g_rel;

__device__ __forceinline__ void gsync(unsigned ph)
{
    __syncthreads();
    if (threadIdx.x == 0) {
        __threadfence();
        const unsigned sub = blockIdx.x & (NSUB - 1);
        const unsigned v = atomicAdd(&g_arr[sub * 32], 1u) + 1u;
        if (v == ph * (unsigned)SUBCNT) {
            const unsigned m = atomicAdd(&g_master, 1u) + 1u;
            if (m == ph * (unsigned)NSUB) atomicExch(&g_rel, ph);
        }
        while (*(volatile unsigned*)&g_rel < ph) { __nanosleep(64); }
        __threadfence();
    }
    __syncthreads();
}

__device__ __forceinline__ uint32_t f2tf32(float x)
{ uint32_t u; asm("cvt.rna.tf32.f32 %0, %1;" : "=r"(u) : "f"(x)); return u; }

__device__ __forceinline__ uint32_t s2u(const void* p)
{ uint32_t a; asm("{ .reg .u64 t; cvta.to.shared.u64 t, %1; cvt.u32.u64 %0, t; }" : "=r"(a) : "l"(p)); return a; }

__device__ __forceinline__ void mma_tf32(float* d,
    uint32_t a0, uint32_t a1, uint32_t a2, uint32_t a3, uint32_t b0, uint32_t b1)
{
    asm volatile(
        "mma.sync.aligned.m16n8k8.row.col.f32.tf32.tf32.f32 "
        "{%0,%1,%2,%3},{%4,%5,%6,%7},{%8,%9},{%0,%1,%2,%3};"
        : "+f"(d[0]), "+f"(d[1]), "+f"(d[2]), "+f"(d[3])
        : "r"(a0), "r"(a1), "r"(a2), "r"(a3), "r"(b0), "r"(b1));
}

struct Params {
    const float *inp;
    const float *Wi_b, *Vd_b, *Wx_b, *V_w, *V_b, *reg_w, *reg_b;
    float* out; float* gb;
};

// C = act(A1@W1^T + A2@W2^T + bias + add1 + add2 + r1u*r1v)
// mode 0 store, 1 tanh, 2 fused LSTM (interleaved gates, out stride 1024), 3 exp+partial sums
// scE != null: A1 is x-source; staging computes x * scE * (1/rowsum(part)) on the fly.
__device__ void gemm64(
    const float* A1, int lda1, const uint32_t* W1, int K1,
    const float* A2, int lda2, const uint32_t* W2, int K2,
    const float* bias, const float* add1, int ld1, const float* add2, int ld2,
    const float* r1u, const float* r1v, const float* cin,
    const float* scE, float* part,
    float* outp, int M, int N, int mode, float* hout, int hstride,
    uint32_t (*As)[64][PAD], uint32_t (*Bs)[64][PAD],
    int vbid, int vgrid)
{
    const int tid = threadIdx.x, wid = tid >> 5, lane = tid & 31;
    const int r4 = lane >> 2, c4 = lane & 3;
    const int wm = (wid >> 1) << 5, wn = (wid & 1) << 5;
    const int srow = tid >> 1, soff = (tid & 1) << 3;
    const int NC = (K1 + K2) >> 4;
    const int nct = N >> 6, ntiles = (M >> 6) * nct;
    const uint32_t sbB = s2u(Bs);

    for (int t = vbid; t < ntiles; t += vgrid) {
        const int m0 = (t / nct) << 6, n0 = (t % nct) << 6;

        float inv = 0.f;
        if (scE) {
            float s = 0.f;
#pragma unroll
            for (int q = 0; q < 16; q++) s += part[(m0 + srow) * 16 + q];
            inv = 1.f / s;
        }

        float acc[2][4][4];
#pragma unroll
        for (int i = 0; i < 2; i++)
#pragma unroll
            for (int j = 0; j < 4; j++)
#pragma unroll
                for (int q = 0; q < 4; q++) acc[i][j][q] = 0.f;

        // prologue: stage chunk 0 (always in segment 1) into buffer 0
        {
            const float* ar = A1 + (size_t)(m0 + srow) * lda1 + soff;
            float4 v0 = *(const float4*)ar, v1 = *(const float4*)(ar + 4);
            if (scE) {
                const float* er = scE + (size_t)(m0 + srow) * 512 + soff;
                float4 e0 = *(const float4*)er, e1 = *(const float4*)(er + 4);
                v0.x *= e0.x * inv; v0.y *= e0.y * inv; v0.z *= e0.z * inv; v0.w *= e0.w * inv;
                v1.x *= e1.x * inv; v1.y *= e1.y * inv; v1.z *= e1.z * inv; v1.w *= e1.w * inv;
            }
            uint4 u0, u1;
            u0.x = f2tf32(v0.x); u0.y = f2tf32(v0.y); u0.z = f2tf32(v0.z); u0.w = f2tf32(v0.w);
            u1.x = f2tf32(v1.x); u1.y = f2tf32(v1.y); u1.z = f2tf32(v1.z); u1.w = f2tf32(v1.w);
            uint32_t* da = &As[0][srow][soff];
            *(uint4*)da = u0; *(uint4*)(da + 4) = u1;
            const uint32_t* wr = W1 + (size_t)(n0 + srow) * K1 + soff;
            const uint32_t d = sbB + (((size_t)0 * 64 + srow) * PAD + soff) * 4;
            asm volatile(
                "cp.async.ca.shared.global [%0],[%1],16;\n\t"
                "cp.async.ca.shared.global [%2],[%3],16;\n\t"
                "cp.async.commit_group;"
                :: "r"(d), "l"(wr), "r"(d + 16), "l"(wr + 4) : "memory");
        }

        for (int c = 0; c < NC; c++) {
            const int b = c & 1, cn = c + 1;
            const int hav = (cn < NC);
            float4 v0, v1;
            const uint32_t* wr = nullptr;
            if (hav) {
                const int kb = cn << 4;
                const float* Ap; int Alda, ko; const uint32_t* Wp; int Wld; int xmm = 0;
                if (kb < K1) { Ap = A1; Alda = lda1; Wp = W1; Wld = K1; ko = kb; xmm = (scE != nullptr); }
                else         { Ap = A2; Alda = lda2; Wp = W2; Wld = K2; ko = kb - K1; }
                const float* ar = Ap + (size_t)(m0 + srow) * Alda + ko + soff;
                v0 = *(const float4*)ar; v1 = *(const float4*)(ar + 4);
                if (xmm) {
                    const float* er = scE + (size_t)(m0 + srow) * 512 + ko + soff;
                    float4 e0 = *(const float4*)er, e1 = *(const float4*)(er + 4);
                    v0.x *= e0.x * inv; v0.y *= e0.y * inv; v0.z *= e0.z * inv; v0.w *= e0.w * inv;
                    v1.x *= e1.x * inv; v1.y *= e1.y * inv; v1.z *= e1.z * inv; v1.w *= e1.w * inv;
                }
                wr = Wp + (size_t)(n0 + srow) * Wld + ko + soff;
            }
            asm volatile("cp.async.wait_group 0;" ::: "memory");
            __syncthreads();
            if (hav) {
                const uint32_t d = sbB + ((((uint32_t)(b ^ 1)) * 64 + srow) * PAD + soff) * 4;
                asm volatile(
                    "cp.async.ca.shared.global [%0],[%1],16;\n\t"
                    "cp.async.ca.shared.global [%2],[%3],16;\n\t"
                    "cp.async.commit_group;"
                    :: "r"(d), "l"(wr), "r"(d + 16), "l"(wr + 4) : "memory");
            }
#pragma unroll
            for (int kk = 0; kk < 2; kk++) {
                uint32_t af[2][4], bf[4][2];
#pragma unroll
                for (int mf = 0; mf < 2; mf++) {
                    const int rr = wm + (mf << 4) + r4, cc = (kk << 3) + c4;
                    af[mf][0] = As[b][rr][cc];     af[mf][1] = As[b][rr + 8][cc];
                    af[mf][2] = As[b][rr][cc + 4]; af[mf][3] = As[b][rr + 8][cc + 4];
                }
#pragma unroll
                for (int nf = 0; nf < 4; nf++) {
                    const int rr = wn + (nf << 3) + r4, cc = (kk << 3) + c4;
                    bf[nf][0] = Bs[b][rr][cc]; bf[nf][1] = Bs[b][rr][cc + 4];
                }
#pragma unroll
                for (int mf = 0; mf < 2; mf++)
#pragma unroll
                    for (int nf = 0; nf < 4; nf++)
                        mma_tf32(acc[mf][nf], af[mf][0], af[mf][1], af[mf][2], af[mf][3],
                                 bf[nf][0], bf[nf][1]);
            }
            if (hav) {
                uint4 u0, u1;
                u0.x = f2tf32(v0.x); u0.y = f2tf32(v0.y); u0.z = f2tf32(v0.z); u0.w = f2tf32(v0.w);
                u1.x = f2tf32(v1.x); u1.y = f2tf32(v1.y); u1.z = f2tf32(v1.z); u1.w = f2tf32(v1.w);
                uint32_t* da = &As[b ^ 1][srow][soff];
                *(uint4*)da = u0; *(uint4*)(da + 4) = u1;
            }
        }
        __syncthreads();

        const int mA0 = m0 + wm, nb0 = n0 + wn;
#pragma unroll
        for (int mf = 0; mf < 2; mf++) {
            const int mA = mA0 + (mf << 4) + r4, mB = mA + 8;
            if (mode <= 1) {
#pragma unroll
                for (int nf = 0; nf < 4; nf++) {
                    const int nc = nb0 + (nf << 3) + (c4 << 1);
                    float x0 = acc[mf][nf][0], x1 = acc[mf][nf][1];
                    float x2 = acc[mf][nf][2], x3 = acc[mf][nf][3];
                    if (bias) { x0 += bias[nc]; x1 += bias[nc + 1]; x2 += bias[nc]; x3 += bias[nc + 1]; }
                    if (add1) {
                        x0 += add1[(size_t)mA * ld1 + nc]; x1 += add1[(size_t)mA * ld1 + nc + 1];
                        x2 += add1[(size_t)mB * ld1 + nc]; x3 += add1[(size_t)mB * ld1 + nc + 1];
                    }
                    if (add2) {
                        x0 += add2[(size_t)mA * ld2 + nc]; x1 += add2[(size_t)mA * ld2 + nc + 1];
                        x2 += add2[(size_t)mB * ld2 + nc]; x3 += add2[(size_t)mB * ld2 + nc + 1];
                    }
                    if (mode == 1) { x0 = tanhf(x0); x1 = tanhf(x1); x2 = tanhf(x2); x3 = tanhf(x3); }
                    *(float2*)(outp + (size_t)mA * N + nc) = make_float2(x0, x1);
                    *(float2*)(outp + (size_t)mB * N + nc) = make_float2(x2, x3);
                }
            } else if (mode == 3) {
                float sA = 0.f, sB = 0.f;
#pragma unroll
                for (int nf = 0; nf < 4; nf++) {
                    const int nc = nb0 + (nf << 3) + (c4 << 1);
                    float x0 = expf(acc[mf][nf][0] + bias[nc]);
                    float x1 = expf(acc[mf][nf][1] + bias[nc + 1]);
                    float x2 = expf(acc[mf][nf][2] + bias[nc]);
                    float x3 = expf(acc[mf][nf][3] + bias[nc + 1]);
                    sA += x0 + x1; sB += x2 + x3;
                    *(float2*)(outp + (size_t)mA * N + nc) = make_float2(x0, x1);
                    *(float2*)(outp + (size_t)mB * N + nc) = make_float2(x2, x3);
                }
                sA += __shfl_xor_sync(0xffffffffu, sA, 1);
                sA += __shfl_xor_sync(0xffffffffu, sA, 2);
                sB += __shfl_xor_sync(0xffffffffu, sB, 1);
                sB += __shfl_xor_sync(0xffffffffu, sB, 2);
                if (c4 == 0) {
                    part[mA * 16 + (nb0 >> 5)] = sA;
                    part[mB * 16 + (nb0 >> 5)] = sB;
                }
            } else {
                const float ra = r1u ? r1u[mA] : 0.f, rb = r1u ? r1u[mB] : 0.f;
#pragma unroll
                for (int nf = 0; nf < 4; nf++) {
                    const int nc = nb0 + (nf << 3) + (c4 << 1);
                    float v00 = acc[mf][nf][0] + bias[nc], v01 = acc[mf][nf][1] + bias[nc + 1];
                    float v10 = acc[mf][nf][2] + bias[nc], v11 = acc[mf][nf][3] + bias[nc + 1];
                    if (r1u) {
                        v00 += ra * r1v[nc]; v01 += ra * r1v[nc + 1];
                        v10 += rb * r1v[nc]; v11 += rb * r1v[nc + 1];
                    }
                    const float t00 = __shfl_xor_sync(0xffffffffu, v00, 1);
                    const float t01 = __shfl_xor_sync(0xffffffffu, v01, 1);
                    const float t10 = __shfl_xor_sync(0xffffffffu, v10, 1);
                    const float t11 = __shfl_xor_sync(0xffffffffu, v11, 1);
                    int m; float fi, ff, fg, fo;
                    if ((c4 & 1) == 0) { m = mA; fi = v00; ff = v01; fg = t00; fo = t01; }
                    else               { m = mB; fi = t10; ff = t11; fg = v10; fo = v11; }
                    const int h = ((nb0 + (nf << 3)) >> 2) + (c4 >> 1);
                    const float cold = cin[(size_t)m * 1024 + 512 + h];
                    const float si = 1.f / (1.f + expf(-fi));
                    const float sf = 1.f / (1.f + expf(-ff));
                    const float so = 1.f / (1.f + expf(-fo));
                    const float c2 = sf * cold + si * tanhf(fg);
                    const float hn = so * tanhf(c2);
                    outp[(size_t)m * 1024 + h] = hn;
                    outp[(size_t)m * 1024 + 512 + h] = c2;
                    if (hout) hout[(size_t)m * hstride + h] = hn;
                }
            }
        }
        __syncthreads();
    }
}

__global__ __launch_bounds__(NTHR) void mega(Params p)
{
    __shared__ uint32_t As[2][64][PAD];
    __shared__ uint32_t Bs[2][64][PAD];
    __shared__ float ssc[LEN];
    const int tid = threadIdx.x, wid = tid >> 5, lane = tid & 31;

    float* gb = p.gb;
    float* wiseq = gb + O_WISEQ;  float* mid2 = gb + O_MID2;  float* ybuf = gb + O_Y;
    float* ht0 = gb + O_HT0;  float* ht1 = gb + O_HT1;
    float* he0 = gb + O_HE0;  float* he1 = gb + O_HE1;
    float* hm0 = gb + O_HM0;  float* hm1 = gb + O_HM1;
    float* decin = gb + O_DECIN;  float* wtwho = gb + O_WTWHO;
    float* tub = gb + O_TU;  float* scE = gb + O_SC;  float* part = gb + O_XM;
    float* lab = gb + O_LAB;
    float* bspi = gb + O_BSPI;  float* btgi = gb + O_BTGI;
    float* bmdi = gb + O_BMDI;  float* wtgci = gb + O_WTGCI;
    const uint32_t* WI32 = (const uint32_t*)(gb + O_WI32);
    const uint32_t* WE32 = (const uint32_t*)(gb + O_WE32);
    const uint32_t* VD32 = (const uint32_t*)(gb + O_VD32);
    const uint32_t* WX32 = (const uint32_t*)(gb + O_WX32);
    const uint32_t* WTWH32 = (const uint32_t*)(gb + O_WTWH32);
    const uint32_t* SPIH = (const uint32_t*)(gb + O_SPIH);
    const uint32_t* SPHH = (const uint32_t*)(gb + O_SPHH);
    const uint32_t* TGX = (const uint32_t*)(gb + O_TGX);
    const uint32_t* TGHH = (const uint32_t*)(gb + O_TGHH);
    const uint32_t* MDIH = (const uint32_t*)(gb + O_MDIH);
    const uint32_t* MDHH = (const uint32_t*)(gb + O_MDHH);

    unsigned ph = 0;

    gemm64(p.inp, 512, WI32, 512, nullptr, 0, nullptr, 0, p.Wi_b,
           nullptr, 0, nullptr, 0, nullptr, nullptr, nullptr, nullptr, nullptr,
           wiseq, BB * LEN, HH, 0, nullptr, 0, As, Bs, blockIdx.x, NBLK);
    gsync(++ph);

    for (int k = 0; k < LOOKN; k++) {
        float* htin  = (k & 1) ? ht1 : ht0;
        float* htout = (k & 1) ? ht0 : ht1;

        gemm64(decin, 512, TGX, 512, htin, K2H, TGHH, 512, btgi,
               nullptr, 0, nullptr, 0, lab, wtgci, htin, nullptr, nullptr,
               htout, BB, H4, 2, nullptr, 0, As, Bs, blockIdx.x, NBLK);
        gsync(++ph);

        if (blockIdx.x < 64) {
            gemm64(htout, K2H, WTWH32, K2H, nullptr, 0, nullptr, 0, nullptr,
                   nullptr, 0, nullptr, 0, nullptr, nullptr, nullptr, nullptr, nullptr,
                   wtwho, BB, K2H, 0, nullptr, 0, As, Bs, blockIdx.x, 64);
        } else if (blockIdx.x == 64) {
            for (int r = wid; r < BB; r += 4) {
                float s = 0.f;
                for (int h = lane; h < HH; h += 32) s += htout[(size_t)r * K2H + h] * p.reg_w[h];
#pragma unroll
                for (int o = 16; o; o >>= 1) s += __shfl_xor_sync(0xffffffffu, s, o);
                if (lane == 0) { const float tv = s + p.reg_b[0]; p.out[r * LOOKN + k] = tv; lab[r] = tv; }
            }
        } else {
            const int base = (blockIdx.x - 65) * NTHR + tid;
            for (int i = base; i < BB * K2H; i += (NBLK - 65) * NTHR) { he0[i] = 0.f; hm0[i] = 0.f; }
        }
        gsync(++ph);

        for (int l = 0; l < LEN; l++) {
            float* hein  = (l & 1) ? he1 : he0;
            float* heout = (l & 1) ? he0 : he1;
            float* hmin  = (l & 1) ? hm1 : hm0;
            float* hmout = (l & 1) ? hm0 : hm1;

            gemm64(hein, K2H, WE32, K2H, nullptr, 0, nullptr, 0, nullptr,
                   wiseq + (size_t)l * HH, LEN * HH, wtwho, K2H,
                   nullptr, nullptr, nullptr, nullptr, nullptr,
                   tub, BB, HH, 1, nullptr, 0, As, Bs, blockIdx.x, NBLK);
            gsync(++ph);
            gemm64(tub, 512, VD32, 512, nullptr, 0, nullptr, 0, p.Vd_b,
                   nullptr, 0, nullptr, 0, nullptr, nullptr, nullptr, nullptr, part,
                   scE, BB, HH, 3, nullptr, 0, As, Bs, blockIdx.x, NBLK);
            gsync(++ph);
            gemm64(p.inp + (size_t)l * 512, LEN * 512, SPIH, 512, hein, K2H, SPHH, 512, bspi,
                   nullptr, 0, nullptr, 0, nullptr, nullptr, hein, scE, part,
                   heout, BB, H4, 2, nullptr, 0, As, Bs, blockIdx.x, NBLK);
            gsync(++ph);
            gemm64(heout, K2H, MDIH, 512, hmin, K2H, MDHH, 512, bmdi,
                   nullptr, 0, nullptr, 0, nullptr, nullptr, hmin, nullptr, nullptr,
                   hmout, BB, H4, 2, mid2 + (size_t)l * HH, LEN * HH,
                   As, Bs, blockIdx.x, NBLK);
            gsync(++ph);
        }

        gemm64(mid2, 512, WX32, 512, nullptr, 0, nullptr, 0, p.Wx_b,
               nullptr, 0, nullptr, 0, nullptr, nullptr, nullptr, nullptr, nullptr,
               ybuf, BB * LEN, HH, 0, nullptr, 0, As, Bs, blockIdx.x, NBLK);
        gsync(++ph);

        if (blockIdx.x < BB) {
            const int b = blockIdx.x;
            for (int l = wid; l < LEN; l += 4) {
                const float* yr = ybuf + ((size_t)b * LEN + l) * HH;
                float pv = 0.f;
                for (int h = lane; h < HH; h += 32)
                    pv += tanhf(wtwho[(size_t)b * K2H + 512 + h] + yr[h]) * p.V_w[h];
#pragma unroll
                for (int o = 16; o; o >>= 1) pv += __shfl_xor_sync(0xffffffffu, pv, o);
                if (lane == 0) ssc[l] = pv + p.V_b[0];
            }
            __syncthreads();
            float a0 = 0.f, a1 = 0.f, a2 = 0.f, a3 = 0.f;
            for (int l = 0; l < LEN; l++) {
                const float s = ssc[l];
                const float* mr = mid2 + ((size_t)b * LEN + l) * HH;
                a0 += s * mr[tid];       a1 += s * mr[tid + 128];
                a2 += s * mr[tid + 256]; a3 += s * mr[tid + 384];
            }
            decin[(size_t)b * HH + tid] = a0;
            decin[(size_t)b * HH + tid + 128] = a1;
            decin[(size_t)b * HH + tid + 256] = a2;
            decin[(size_t)b * HH + tid + 384] = a3;
        }
        gsync(++ph);
    }
}

__global__ __launch_bounds__(256) void prep_k(
    const float* bihsp, const float* bhhsp, const float* bihtg, const float* bhhtg,
    const float* bihmid, const float* bhhmid, const float* wihtg,
    const float* wtw, const float* whw,
    const float* wisp, const float* whsp, const float* whtg,
    const float* wimd, const float* whmd,
    const float* wiw, const float* wew, const float* vdw, const float* wxw)
{
    const int nt = gridDim.x * 256;
    const int gid = blockIdx.x * 256 + threadIdx.x;
    uint32_t* WI32 = (uint32_t*)(g_buf + O_WI32);
    uint32_t* WE32 = (uint32_t*)(g_buf + O_WE32);
    uint32_t* VD32 = (uint32_t*)(g_buf + O_VD32);
    uint32_t* WX32 = (uint32_t*)(g_buf + O_WX32);
    uint32_t* WTWH32 = (uint32_t*)(g_buf + O_WTWH32);
    uint32_t* SPIH = (uint32_t*)(g_buf + O_SPIH);
    uint32_t* SPHH = (uint32_t*)(g_buf + O_SPHH);
    uint32_t* TGX = (uint32_t*)(g_buf + O_TGX);
    uint32_t* TGHH = (uint32_t*)(g_buf + O_TGHH);
    uint32_t* MDIH = (uint32_t*)(g_buf + O_MDIH);
    uint32_t* MDHH = (uint32_t*)(g_buf + O_MDHH);

    for (int i = gid; i < 512*512; i += nt) {
        WI32[i] = f2tf32(wiw[i]);
        VD32[i] = f2tf32(vdw[i]);
        WX32[i] = f2tf32(wxw[i]);
    }
    for (int i = gid; i < 512*1024; i += nt) WE32[i] = f2tf32(wew[i]);
    for (int i = gid; i < 1024*1024; i += nt) {
        const int r = i >> 10, c = i & 1023;
        WTWH32[i] = f2tf32(r < 512 ? wtw[(size_t)r*1024 + c] : whw[(size_t)(r-512)*1024 + c]);
    }
    for (int i = gid; i < H4*512; i += nt) {
        const int rp = i >> 9, kk = i & 511;
        const int h = rp >> 2, gg = rp & 3;
        const size_t src = (size_t)(gg * 512 + h);
        SPIH[i] = f2tf32(wisp[src*512 + kk]);
        SPHH[i] = f2tf32(whsp[src*512 + kk]);
        TGHH[i] = f2tf32(whtg[src*512 + kk]);
        MDIH[i] = f2tf32(wimd[src*512 + kk]);
        MDHH[i] = f2tf32(whmd[src*512 + kk]);
        TGX[i]  = f2tf32(wihtg[src*513 + 1 + kk]);
    }
    for (int i = gid; i < H4; i += nt) {
        const int h = i >> 2, gg = i & 3;
        const int s = gg * 512 + h;
        g_buf[O_BSPI + i]  = bihsp[s] + bhhsp[s];
        g_buf[O_BTGI + i]  = bihtg[s] + bhhtg[s];
        g_buf[O_BMDI + i]  = bihmid[s] + bhhmid[s];
        g_buf[O_WTGCI + i] = wihtg[(size_t)s * 513];
    }
}

__global__ __launch_bounds__(256) void init_k(const float* __restrict__ labp)
{
    const int i = blockIdx.x * 256 + threadIdx.x;
    if (i < NSUB) g_arr[i * 32] = 0u;
    if (i == NSUB) g_master = 0u;
    if (i == NSUB + 1) g_rel = 0u;
    if (i < BB * K2H) g_buf[O_HT0 + i] = 0.f;
    if (i < BB * HH)  g_buf[O_DECIN + i] = 0.f;
    if (i < BB)       g_buf[O_LAB + i] = labp[(size_t)i * LABW + STARTI];
}

extern "C" void kernel_launch(void* const* d_in, const int* in_sizes, int n_in,
                              void* d_out, int out_size)
{
    Params p;
    p.inp   = (const float*)d_in[0];
    p.Wi_b  = (const float*)d_in[15];
    p.Vd_b  = (const float*)d_in[19];
    p.Wx_b  = (const float*)d_in[21];
    p.V_w   = (const float*)d_in[23];
    p.V_b   = (const float*)d_in[24];
    p.reg_w = (const float*)d_in[25];
    p.reg_b = (const float*)d_in[26];
    p.out   = (float*)d_out;

    float* gb = nullptr;
    cudaGetSymbolAddress((void**)&gb, g_buf);
    p.gb = gb;

    prep_k<<<2048, 256>>>(
        (const float*)d_in[4], (const float*)d_in[5], (const float*)d_in[8],
        (const float*)d_in[9], (const float*)d_in[12], (const float*)d_in[13],
        (const float*)d_in[6], (const float*)d_in[17], (const float*)d_in[22],
        (const float*)d_in[2], (const float*)d_in[3], (const float*)d_in[7],
        (const float*)d_in[10], (const float*)d_in[11],
        (const float*)d_in[14], (const float*)d_in[16],
        (const float*)d_in[18], (const float*)d_in[20]);
    init_k<<<(BB * K2H + 255) / 256, 256>>>((const float*)d_in[1]);
    mega<<<NBLK, NTHR>>>(p);
}

// round 11
// speedup vs baseline: 1.6333x; 1.6333x over previous
#include <cuda_runtime.h>
#include <cuda_fp16.h>
#include <math.h>
#include <stdint.h>

#define BB 256
#define HH 512
#define H4 2048
#define LEN 48
#define LOOKN 10
#define K2H 1024
#define STARTI 48
#define LABW 58
#define NBLK 296
#define NTHR 128
#define NSUB 8
#define SUBCNT 37
#define PADU 36
#define BOFF (2*64*PADU)
#define SMEMB (4*64*PADU*4)

constexpr size_t O_WISEQ = 0;
constexpr size_t O_MID2  = O_WISEQ + (size_t)BB*LEN*HH;
constexpr size_t O_Y     = O_MID2  + (size_t)BB*LEN*HH;
constexpr size_t O_HT0   = O_Y     + (size_t)BB*LEN*HH;
constexpr size_t O_HT1   = O_HT0   + (size_t)BB*K2H;
constexpr size_t O_HE0   = O_HT1   + (size_t)BB*K2H;
constexpr size_t O_HE1   = O_HE0   + (size_t)BB*K2H;
constexpr size_t O_HM0   = O_HE1   + (size_t)BB*K2H;
constexpr size_t O_HM1   = O_HM0   + (size_t)BB*K2H;
constexpr size_t O_DECIN = O_HM1   + (size_t)BB*K2H;
constexpr size_t O_WTWHO = O_DECIN + (size_t)BB*HH;
constexpr size_t O_TU    = O_WTWHO + (size_t)BB*K2H;
constexpr size_t O_SC    = O_TU    + (size_t)BB*HH;
constexpr size_t O_XM    = O_SC    + (size_t)BB*HH;
constexpr size_t O_LAB   = O_XM    + (size_t)BB*HH;
constexpr size_t O_BSPI  = O_LAB   + 1024;
constexpr size_t O_BTGI  = O_BSPI  + H4;
constexpr size_t O_BMDI  = O_BTGI  + H4;
constexpr size_t O_WTGCI = O_BMDI  + H4;
constexpr size_t O_WI16  = O_WTGCI + H4;
constexpr size_t O_WE16  = O_WI16  + (size_t)512*512;
constexpr size_t O_VD16  = O_WE16  + (size_t)512*1024;
constexpr size_t O_WX16  = O_VD16  + (size_t)512*512;
constexpr size_t O_WTWH16= O_WX16  + (size_t)512*512;
constexpr size_t O_SPIH  = O_WTWH16+ (size_t)1024*1024;
constexpr size_t O_SPHH  = O_SPIH  + (size_t)H4*512;
constexpr size_t O_TGX   = O_SPHH  + (size_t)H4*512;
constexpr size_t O_TGHH  = O_TGX   + (size_t)H4*512;
constexpr size_t O_MDIH  = O_TGHH  + (size_t)H4*512;
constexpr size_t O_MDHH  = O_MDIH  + (size_t)H4*512;
constexpr size_t G_TOTAL = O_MDHH  + (size_t)H4*512;

__device__ float g_buf[G_TOTAL];
__device__ __align__(128) unsigned g_arr[NSUB * 32];
__device__ unsigned g_master;
__device__ unsigned g_rel;

__device__ __forceinline__ void gsync(unsigned ph)
{
    __syncthreads();
    if (threadIdx.x == 0) {
        __threadfence();
        const unsigned sub = blockIdx.x & (NSUB - 1);
        const unsigned v = atomicAdd(&g_arr[sub * 32], 1u) + 1u;
        if (v == ph * (unsigned)SUBCNT) {
            const unsigned m = atomicAdd(&g_master, 1u) + 1u;
            if (m == ph * (unsigned)NSUB) atomicExch(&g_rel, ph);
        }
        while (*(volatile unsigned*)&g_rel < ph) { __nanosleep(64); }
        __threadfence();
    }
    __syncthreads();
}

__device__ __forceinline__ uint32_t s2u(const void* p)
{ uint32_t a; asm("{ .reg .u64 t; cvta.to.shared.u64 t, %1; cvt.u32.u64 %0, t; }" : "=r"(a) : "l"(p)); return a; }

__device__ __forceinline__ void mma_f16(float* d,
    uint32_t a0, uint32_t a1, uint32_t a2, uint32_t a3, uint32_t b0, uint32_t b1)
{
    asm volatile(
        "mma.sync.aligned.m16n8k16.row.col.f32.f16.f16.f32 "
        "{%0,%1,%2,%3},{%4,%5,%6,%7},{%8,%9},{%0,%1,%2,%3};"
        : "+f"(d[0]), "+f"(d[1]), "+f"(d[2]), "+f"(d[3])
        : "r"(a0), "r"(a1), "r"(a2), "r"(a3), "r"(b0), "r"(b1));
}

struct Params {
    const float *inp;
    const float *Wi_b, *Vd_b, *Wx_b, *V_w, *V_b, *reg_w, *reg_b;
    float* out; float* gb;
};

__device__ __forceinline__ void ldA(const float* Ap, int lda, const float* Ep,
                                    float4* pa, float4* pe,
                                    int m0, int srow, int ko, int shalf, int em)
{
    const float* ar = Ap + (size_t)(m0 + srow) * lda + ko + shalf * 32;
#pragma unroll
    for (int i = 0; i < 8; i++) pa[i] = ((const float4*)ar)[i];
    if (em) {
        const float* er = Ep + (size_t)(m0 + srow) * 512 + ko + shalf * 32;
#pragma unroll
        for (int i = 0; i < 8; i++) pe[i] = ((const float4*)er)[i];
    }
}

__device__ __forceinline__ void stA(uint32_t* dsm, int buf, int srow, int shalf,
                                    const float4* pa, const float4* pe, int em, float inv)
{
    uint32_t* da = dsm + ((buf * 64 + srow) * PADU + shalf * 16);
#pragma unroll
    for (int i = 0; i < 8; i++) {
        float4 v = pa[i];
        if (em) { float4 e = pe[i]; v.x *= e.x * inv; v.y *= e.y * inv; v.z *= e.z * inv; v.w *= e.w * inv; }
        __half2 h0 = __floats2half2_rn(v.x, v.y);
        __half2 h1 = __floats2half2_rn(v.z, v.w);
        da[i * 2]     = *(uint32_t*)&h0;
        da[i * 2 + 1] = *(uint32_t*)&h1;
    }
}

__device__ __forceinline__ void cpB(uint32_t sbB, int buf, int srow, int shalf,
                                    const uint16_t* Wp, int Wld, int n0, int ko)
{
    const uint16_t* wr = Wp + (size_t)(n0 + srow) * Wld + ko + shalf * 32;
    const uint32_t d = sbB + ((buf * 64 + srow) * PADU + shalf * 16) * 4;
    asm volatile(
        "cp.async.ca.shared.global [%0],[%4],16;\n\t"
        "cp.async.ca.shared.global [%1],[%5],16;\n\t"
        "cp.async.ca.shared.global [%2],[%6],16;\n\t"
        "cp.async.ca.shared.global [%3],[%7],16;\n\t"
        "cp.async.commit_group;"
        :: "r"(d), "r"(d + 16), "r"(d + 32), "r"(d + 48),
           "l"(wr), "l"(wr + 8), "l"(wr + 16), "l"(wr + 24) : "memory");
}

// C = act(A1@W1^T + A2@W2^T + bias + add1 + add2 + r1u*r1v)
// mode 0 store, 1 tanh, 2 fused LSTM (interleaved gates), 3 exp + partial sums
__device__ void gemm16(
    const float* A1, int lda1, const uint16_t* W1, int K1,
    const float* A2, int lda2, const uint16_t* W2, int K2,
    const float* bias, const float* add1, int ld1, const float* add2, int ld2,
    const float* r1u, const float* r1v, const float* cin,
    const float* scE, float* part,
    float* outp, int M, int N, int mode, float* hout, int hstride,
    uint32_t* dsm, int vbid, int vgrid)
{
    const int tid = threadIdx.x, wid = tid >> 5, lane = tid & 31;
    const int g = lane >> 2, c4 = lane & 3;
    const int wm = (wid >> 1) << 5, wn = (wid & 1) << 5;
    const int srow = tid >> 1, shalf = tid & 1;
    const int NC = (K1 + K2) >> 6;
    const int nct = N >> 6, ntiles = (M >> 6) * nct;
    const uint32_t sbB = s2u(dsm) + BOFF * 4;
    uint32_t* Bsm = dsm + BOFF;

    for (int t = vbid; t < ntiles; t += vgrid) {
        const int m0 = (t / nct) << 6, n0 = (t % nct) << 6;

        float inv = 0.f;
        if (scE) {
            float s = 0.f;
#pragma unroll
            for (int q = 0; q < 16; q++) s += part[(m0 + srow) * 16 + q];
            inv = 1.f / s;
        }

        float acc[2][4][4];
#pragma unroll
        for (int i = 0; i < 2; i++)
#pragma unroll
            for (int j = 0; j < 4; j++)
#pragma unroll
                for (int q = 0; q < 4; q++) acc[i][j][q] = 0.f;

        float4 pa[8], pe[8];
        // prologue: chunk 0 always in segment 1
        ldA(A1, lda1, scE, pa, pe, m0, srow, 0, shalf, scE != nullptr);
        cpB(sbB, 0, srow, shalf, W1, K1, n0, 0);
        stA(dsm, 0, srow, shalf, pa, pe, scE != nullptr, inv);

        for (int c = 0; c < NC; c++) {
            const int b = c & 1;
            const int hav = (c + 1 < NC);
            const uint16_t* Wp2 = nullptr; int Wld2 = 0, ko2 = 0, em2 = 0;
            if (hav) {
                const int kb = (c + 1) << 6;
                const float* Ap; int Alda;
                if (kb < K1) { Ap = A1; Alda = lda1; Wp2 = W1; Wld2 = K1; ko2 = kb; em2 = (scE != nullptr); }
                else         { Ap = A2; Alda = lda2; Wp2 = W2; Wld2 = K2; ko2 = kb - K1; em2 = 0; }
                ldA(Ap, Alda, scE, pa, pe, m0, srow, ko2, shalf, em2);
            }
            asm volatile("cp.async.wait_group 0;" ::: "memory");
            __syncthreads();
            if (hav) cpB(sbB, (c + 1) & 1, srow, shalf, Wp2, Wld2, n0, ko2);

#pragma unroll
            for (int ks = 0; ks < 4; ks++) {
                uint32_t af[2][4], bf[4][2];
#pragma unroll
                for (int mf = 0; mf < 2; mf++) {
                    const int row = wm + (mf << 4) + g;
                    const uint32_t* ab = dsm + (b * 64 + row) * PADU + ks * 8;
                    const uint32_t* ab8 = dsm + (b * 64 + row + 8) * PADU + ks * 8;
                    af[mf][0] = ab[c4];   af[mf][1] = ab8[c4];
                    af[mf][2] = ab[c4+4]; af[mf][3] = ab8[c4+4];
                }
#pragma unroll
                for (int nf = 0; nf < 4; nf++) {
                    const int r = wn + (nf << 3) + g;
                    const uint32_t* bb = Bsm + (b * 64 + r) * PADU + ks * 8;
                    bf[nf][0] = bb[c4]; bf[nf][1] = bb[c4 + 4];
                }
#pragma unroll
                for (int mf = 0; mf < 2; mf++)
#pragma unroll
                    for (int nf = 0; nf < 4; nf++)
                        mma_f16(acc[mf][nf], af[mf][0], af[mf][1], af[mf][2], af[mf][3],
                                bf[nf][0], bf[nf][1]);
            }
            if (hav) stA(dsm, (c + 1) & 1, srow, shalf, pa, pe, em2, inv);
        }

        const int mA0 = m0 + wm, nb0 = n0 + wn;
#pragma unroll
        for (int mf = 0; mf < 2; mf++) {
            const int mA = mA0 + (mf << 4) + g, mB = mA + 8;
            if (mode <= 1) {
#pragma unroll
                for (int nf = 0; nf < 4; nf++) {
                    const int nc = nb0 + (nf << 3) + (c4 << 1);
                    float x0 = acc[mf][nf][0], x1 = acc[mf][nf][1];
                    float x2 = acc[mf][nf][2], x3 = acc[mf][nf][3];
                    if (bias) { x0 += bias[nc]; x1 += bias[nc + 1]; x2 += bias[nc]; x3 += bias[nc + 1]; }
                    if (add1) {
                        x0 += add1[(size_t)mA * ld1 + nc]; x1 += add1[(size_t)mA * ld1 + nc + 1];
                        x2 += add1[(size_t)mB * ld1 + nc]; x3 += add1[(size_t)mB * ld1 + nc + 1];
                    }
                    if (add2) {
                        x0 += add2[(size_t)mA * ld2 + nc]; x1 += add2[(size_t)mA * ld2 + nc + 1];
                        x2 += add2[(size_t)mB * ld2 + nc]; x3 += add2[(size_t)mB * ld2 + nc + 1];
                    }
                    if (mode == 1) { x0 = tanhf(x0); x1 = tanhf(x1); x2 = tanhf(x2); x3 = tanhf(x3); }
                    *(float2*)(outp + (size_t)mA * N + nc) = make_float2(x0, x1);
                    *(float2*)(outp + (size_t)mB * N + nc) = make_float2(x2, x3);
                }
            } else if (mode == 3) {
                float sA = 0.f, sB = 0.f;
#pragma unroll
                for (int nf = 0; nf < 4; nf++) {
                    const int nc = nb0 + (nf << 3) + (c4 << 1);
                    float x0 = expf(acc[mf][nf][0] + bias[nc]);
                    float x1 = expf(acc[mf][nf][1] + bias[nc + 1]);
                    float x2 = expf(acc[mf][nf][2] + bias[nc]);
                    float x3 = expf(acc[mf][nf][3] + bias[nc + 1]);
                    sA += x0 + x1; sB += x2 + x3;
                    *(float2*)(outp + (size_t)mA * N + nc) = make_float2(x0, x1);
                    *(float2*)(outp + (size_t)mB * N + nc) = make_float2(x2, x3);
                }
                sA += __shfl_xor_sync(0xffffffffu, sA, 1);
                sA += __shfl_xor_sync(0xffffffffu, sA, 2);
                sB += __shfl_xor_sync(0xffffffffu, sB, 1);
                sB += __shfl_xor_sync(0xffffffffu, sB, 2);
                if (c4 == 0) {
                    part[mA * 16 + (nb0 >> 5)] = sA;
                    part[mB * 16 + (nb0 >> 5)] = sB;
                }
            } else {
                const float ra = r1u ? r1u[mA] : 0.f, rb = r1u ? r1u[mB] : 0.f;
#pragma unroll
                for (int nf = 0; nf < 4; nf++) {
                    const int nc = nb0 + (nf << 3) + (c4 << 1);
                    float v00 = acc[mf][nf][0] + bias[nc], v01 = acc[mf][nf][1] + bias[nc + 1];
                    float v10 = acc[mf][nf][2] + bias[nc], v11 = acc[mf][nf][3] + bias[nc + 1];
                    if (r1u) {
                        v00 += ra * r1v[nc]; v01 += ra * r1v[nc + 1];
                        v10 += rb * r1v[nc]; v11 += rb * r1v[nc + 1];
                    }
                    const float t00 = __shfl_xor_sync(0xffffffffu, v00, 1);
                    const float t01 = __shfl_xor_sync(0xffffffffu, v01, 1);
                    const float t10 = __shfl_xor_sync(0xffffffffu, v10, 1);
                    const float t11 = __shfl_xor_sync(0xffffffffu, v11, 1);
                    int m; float fi, ff, fg, fo;
                    if ((c4 & 1) == 0) { m = mA; fi = v00; ff = v01; fg = t00; fo = t01; }
                    else               { m = mB; fi = t10; ff = t11; fg = v10; fo = v11; }
                    const int h = ((nb0 + (nf << 3)) >> 2) + (c4 >> 1);
                    const float cold = cin[(size_t)m * 1024 + 512 + h];
                    const float si = 1.f / (1.f + expf(-fi));
                    const float sf = 1.f / (1.f + expf(-ff));
                    const float so = 1.f / (1.f + expf(-fo));
                    const float c2 = sf * cold + si * tanhf(fg);
                    const float hn = so * tanhf(c2);
                    outp[(size_t)m * 1024 + h] = hn;
                    outp[(size_t)m * 1024 + 512 + h] = c2;
                    if (hout) hout[(size_t)m * hstride + h] = hn;
                }
            }
        }
        __syncthreads();
    }
}

__global__ __launch_bounds__(NTHR) void mega(Params p)
{
    extern __shared__ uint32_t dsm[];
    __shared__ float ssc[LEN];
    const int tid = threadIdx.x, wid = tid >> 5, lane = tid & 31;

    float* gb = p.gb;
    float* wiseq = gb + O_WISEQ;  float* mid2 = gb + O_MID2;  float* ybuf = gb + O_Y;
    float* ht0 = gb + O_HT0;  float* ht1 = gb + O_HT1;
    float* he0 = gb + O_HE0;  float* he1 = gb + O_HE1;
    float* hm0 = gb + O_HM0;  float* hm1 = gb + O_HM1;
    float* decin = gb + O_DECIN;  float* wtwho = gb + O_WTWHO;
    float* tub = gb + O_TU;  float* scE = gb + O_SC;  float* part = gb + O_XM;
    float* lab = gb + O_LAB;
    float* bspi = gb + O_BSPI;  float* btgi = gb + O_BTGI;
    float* bmdi = gb + O_BMDI;  float* wtgci = gb + O_WTGCI;
    const uint16_t* WI16 = (const uint16_t*)(gb + O_WI16);
    const uint16_t* WE16 = (const uint16_t*)(gb + O_WE16);
    const uint16_t* VD16 = (const uint16_t*)(gb + O_VD16);
    const uint16_t* WX16 = (const uint16_t*)(gb + O_WX16);
    const uint16_t* WTWH16 = (const uint16_t*)(gb + O_WTWH16);
    const uint16_t* SPIH = (const uint16_t*)(gb + O_SPIH);
    const uint16_t* SPHH = (const uint16_t*)(gb + O_SPHH);
    const uint16_t* TGX = (const uint16_t*)(gb + O_TGX);
    const uint16_t* TGHH = (const uint16_t*)(gb + O_TGHH);
    const uint16_t* MDIH = (const uint16_t*)(gb + O_MDIH);
    const uint16_t* MDHH = (const uint16_t*)(gb + O_MDHH);

    unsigned ph = 0;

    gemm16(p.inp, 512, WI16, 512, nullptr, 0, nullptr, 0, p.Wi_b,
           nullptr, 0, nullptr, 0, nullptr, nullptr, nullptr, nullptr, nullptr,
           wiseq, BB * LEN, HH, 0, nullptr, 0, dsm, blockIdx.x, NBLK);
    gsync(++ph);

    for (int k = 0; k < LOOKN; k++) {
        float* htin  = (k & 1) ? ht1 : ht0;
        float* htout = (k & 1) ? ht0 : ht1;

        gemm16(decin, 512, TGX, 512, htin, K2H, TGHH, 512, btgi,
               nullptr, 0, nullptr, 0, lab, wtgci, htin, nullptr, nullptr,
               htout, BB, H4, 2, nullptr, 0, dsm, blockIdx.x, NBLK);
        gsync(++ph);

        if (blockIdx.x < 64) {
            gemm16(htout, K2H, WTWH16, K2H, nullptr, 0, nullptr, 0, nullptr,
                   nullptr, 0, nullptr, 0, nullptr, nullptr, nullptr, nullptr, nullptr,
                   wtwho, BB, K2H, 0, nullptr, 0, dsm, blockIdx.x, 64);
        } else if (blockIdx.x == 64) {
            for (int r = wid; r < BB; r += 4) {
                float s = 0.f;
                for (int h = lane; h < HH; h += 32) s += htout[(size_t)r * K2H + h] * p.reg_w[h];
#pragma unroll
                for (int o = 16; o; o >>= 1) s += __shfl_xor_sync(0xffffffffu, s, o);
                if (lane == 0) { const float tv = s + p.reg_b[0]; p.out[r * LOOKN + k] = tv; lab[r] = tv; }
            }
        } else {
            const int base = (blockIdx.x - 65) * NTHR + tid;
            for (int i = base; i < BB * K2H; i += (NBLK - 65) * NTHR) { he0[i] = 0.f; hm0[i] = 0.f; }
        }
        gsync(++ph);

        // prologue: tu(0), sc(0)
        gemm16(he0, K2H, WE16, K2H, nullptr, 0, nullptr, 0, nullptr,
               wiseq, LEN * HH, wtwho, K2H, nullptr, nullptr, nullptr, nullptr, nullptr,
               tub, BB, HH, 1, nullptr, 0, dsm, blockIdx.x, NBLK);
        gsync(++ph);
        gemm16(tub, 512, VD16, 512, nullptr, 0, nullptr, 0, p.Vd_b,
               nullptr, 0, nullptr, 0, nullptr, nullptr, nullptr, nullptr, part,
               scE, BB, HH, 3, nullptr, 0, dsm, blockIdx.x, NBLK);
        gsync(++ph);

        for (int l = 0; l < LEN; l++) {
            float* hein  = (l & 1) ? he1 : he0;
            float* heout = (l & 1) ? he0 : he1;
            float* hmin  = (l & 1) ? hm1 : hm0;
            float* hmout = (l & 1) ? hm0 : hm1;

            // sp(l)
            gemm16(p.inp + (size_t)l * 512, LEN * 512, SPIH, 512, hein, K2H, SPHH, 512, bspi,
                   nullptr, 0, nullptr, 0, nullptr, nullptr, hein, scE, part,
                   heout, BB, H4, 2, nullptr, 0, dsm, blockIdx.x, NBLK);
            gsync(++ph);

            // mid(l) || tu(l+1)
            if (blockIdx.x < 160) {
                gemm16(heout, K2H, MDIH, 512, hmin, K2H, MDHH, 512, bmdi,
                       nullptr, 0, nullptr, 0, nullptr, nullptr, hmin, nullptr, nullptr,
                       hmout, BB, H4, 2, mid2 + (size_t)l * HH, LEN * HH,
                       dsm, blockIdx.x, 160);
            } else if (l < LEN - 1) {
                gemm16(heout, K2H, WE16, K2H, nullptr, 0, nullptr, 0, nullptr,
                       wiseq + (size_t)(l + 1) * HH, LEN * HH, wtwho, K2H,
                       nullptr, nullptr, nullptr, nullptr, nullptr,
                       tub, BB, HH, 1, nullptr, 0, dsm, blockIdx.x - 160, 136);
            }
            gsync(++ph);

            // sc(l+1)
            if (l < LEN - 1) {
                gemm16(tub, 512, VD16, 512, nullptr, 0, nullptr, 0, p.Vd_b,
                       nullptr, 0, nullptr, 0, nullptr, nullptr, nullptr, nullptr, part,
                       scE, BB, HH, 3, nullptr, 0, dsm, blockIdx.x, NBLK);
                gsync(++ph);
            }
        }

        gemm16(mid2, 512, WX16, 512, nullptr, 0, nullptr, 0, p.Wx_b,
               nullptr, 0, nullptr, 0, nullptr, nullptr, nullptr, nullptr, nullptr,
               ybuf, BB * LEN, HH, 0, nullptr, 0, dsm, blockIdx.x, NBLK);
        gsync(++ph);

        if (blockIdx.x < BB) {
            const int b = blockIdx.x;
            for (int l = wid; l < LEN; l += 4) {
                const float* yr = ybuf + ((size_t)b * LEN + l) * HH;
                float pv = 0.f;
                for (int h = lane; h < HH; h += 32)
                    pv += tanhf(wtwho[(size_t)b * K2H + 512 + h] + yr[h]) * p.V_w[h];
#pragma unroll
                for (int o = 16; o; o >>= 1) pv += __shfl_xor_sync(0xffffffffu, pv, o);
                if (lane == 0) ssc[l] = pv + p.V_b[0];
            }
            __syncthreads();
            float a0 = 0.f, a1 = 0.f, a2 = 0.f, a3 = 0.f;
            for (int l = 0; l < LEN; l++) {
                const float s = ssc[l];
                const float* mr = mid2 + ((size_t)b * LEN + l) * HH;
                a0 += s * mr[tid];       a1 += s * mr[tid + 128];
                a2 += s * mr[tid + 256]; a3 += s * mr[tid + 384];
            }
            decin[(size_t)b * HH + tid] = a0;
            decin[(size_t)b * HH + tid + 128] = a1;
            decin[(size_t)b * HH + tid + 256] = a2;
            decin[(size_t)b * HH + tid + 384] = a3;
        }
        gsync(++ph);
    }
}

__global__ __launch_bounds__(256) void prep_k(
    const float* bihsp, const float* bhhsp, const float* bihtg, const float* bhhtg,
    const float* bihmid, const float* bhhmid, const float* wihtg,
    const float* wtw, const float* whw,
    const float* wisp, const float* whsp, const float* whtg,
    const float* wimd, const float* whmd,
    const float* wiw, const float* wew, const float* vdw, const float* wxw)
{
    const int nt = gridDim.x * 256;
    const int gid = blockIdx.x * 256 + threadIdx.x;
    __half* WI16 = (__half*)(g_buf + O_WI16);
    __half* WE16 = (__half*)(g_buf + O_WE16);
    __half* VD16 = (__half*)(g_buf + O_VD16);
    __half* WX16 = (__half*)(g_buf + O_WX16);
    __half* WTWH16 = (__half*)(g_buf + O_WTWH16);
    __half* SPIH = (__half*)(g_buf + O_SPIH);
    __half* SPHH = (__half*)(g_buf + O_SPHH);
    __half* TGX = (__half*)(g_buf + O_TGX);
    __half* TGHH = (__half*)(g_buf + O_TGHH);
    __half* MDIH = (__half*)(g_buf + O_MDIH);
    __half* MDHH = (__half*)(g_buf + O_MDHH);

    for (int i = gid; i < 512*512; i += nt) {
        WI16[i] = __float2half_rn(wiw[i]);
        VD16[i] = __float2half_rn(vdw[i]);
        WX16[i] = __float2half_rn(wxw[i]);
    }
    for (int i = gid; i < 512*1024; i += nt) WE16[i] = __float2half_rn(wew[i]);
    for (int i = gid; i < 1024*1024; i += nt) {
        const int r = i >> 10, c = i & 1023;
        WTWH16[i] = __float2half_rn(r < 512 ? wtw[(size_t)r*1024 + c] : whw[(size_t)(r-512)*1024 + c]);
    }
    for (int i = gid; i < H4*512; i += nt) {
        const int rp = i >> 9, kk = i & 511;
        const int h = rp >> 2, gg = rp & 3;
        const size_t src = (size_t)(gg * 512 + h);
        SPIH[i] = __float2half_rn(wisp[src*512 + kk]);
        SPHH[i] = __float2half_rn(whsp[src*512 + kk]);
        TGHH[i] = __float2half_rn(whtg[src*512 + kk]);
        MDIH[i] = __float2half_rn(wimd[src*512 + kk]);
        MDHH[i] = __float2half_rn(whmd[src*512 + kk]);
        TGX[i]  = __float2half_rn(wihtg[src*513 + 1 + kk]);
    }
    for (int i = gid; i < H4; i += nt) {
        const int h = i >> 2, gg = i & 3;
        const int s = gg * 512 + h;
        g_buf[O_BSPI + i]  = bihsp[s] + bhhsp[s];
        g_buf[O_BTGI + i]  = bihtg[s] + bhhtg[s];
        g_buf[O_BMDI + i]  = bihmid[s] + bhhmid[s];
        g_buf[O_WTGCI + i] = wihtg[(size_t)s * 513];
    }
}

__global__ __launch_bounds__(256) void init_k(const float* __restrict__ labp)
{
    const int i = blockIdx.x * 256 + threadIdx.x;
    if (i < NSUB) g_arr[i * 32] = 0u;
    if (i == NSUB) g_master = 0u;
    if (i == NSUB + 1) g_rel = 0u;
    if (i < BB * K2H) g_buf[O_HT0 + i] = 0.f;
    if (i < BB * HH)  g_buf[O_DECIN + i] = 0.f;
    if (i < BB)       g_buf[O_LAB + i] = labp[(size_t)i * LABW + STARTI];
}

extern "C" void kernel_launch(void* const* d_in, const int* in_sizes, int n_in,
                              void* d_out, int out_size)
{
    Params p;
    p.inp   = (const float*)d_in[0];
    p.Wi_b  = (const float*)d_in[15];
    p.Vd_b  = (const float*)d_in[19];
    p.Wx_b  = (const float*)d_in[21];
    p.V_w   = (const float*)d_in[23];
    p.V_b   = (const float*)d_in[24];
    p.reg_w = (const float*)d_in[25];
    p.reg_b = (const float*)d_in[26];
    p.out   = (float*)d_out;

    float* gb = nullptr;
    cudaGetSymbolAddress((void**)&gb, g_buf);
    p.gb = gb;

    cudaFuncSetAttribute(mega, cudaFuncAttributeMaxDynamicSharedMemorySize, SMEMB);

    prep_k<<<2048, 256>>>(
        (const float*)d_in[4], (const float*)d_in[5], (const float*)d_in[8],
        (const float*)d_in[9], (const float*)d_in[12], (const float*)d_in[13],
        (const float*)d_in[6], (const float*)d_in[17], (const float*)d_in[22],
        (const float*)d_in[2], (const float*)d_in[3], (const float*)d_in[7],
        (const float*)d_in[10], (const float*)d_in[11],
        (const float*)d_in[14], (const float*)d_in[16],
        (const float*)d_in[18], (const float*)d_in[20]);
    init_k<<<(BB * K2H + 255) / 256, 256>>>((const float*)d_in[1]);
    mega<<<NBLK, NTHR, SMEMB>>>(p);
}

// round 12
// speedup vs baseline: 2.2218x; 1.3603x over previous
#include <cuda_runtime.h>
#include <cuda_fp16.h>
#include <math.h>
#include <stdint.h>

#define BB 256
#define HH 512
#define H4 2048
#define LEN 48
#define LOOKN 10
#define K2H 1024
#define STARTI 48
#define LABW 58
#define NBLK 296
#define NTHR 128
#define NSUB 8
#define SUBCNT 37
#define PADU 36
#define ABUFS (4*64*PADU)
#define SMEMB (2*ABUFS*4)

// ---- scratch layout (float slots; fp16 data packed 2/slot) ----
constexpr size_t O_WISEQ = 0;
constexpr size_t O_MID2  = O_WISEQ + (size_t)BB*LEN*HH;
constexpr size_t O_Y     = O_MID2  + (size_t)BB*LEN*HH;
constexpr size_t O_HT0   = O_Y     + (size_t)BB*LEN*HH;
constexpr size_t O_HT1   = O_HT0   + (size_t)BB*K2H;
constexpr size_t O_HE0   = O_HT1   + (size_t)BB*K2H;
constexpr size_t O_HE1   = O_HE0   + (size_t)BB*K2H;
constexpr size_t O_HM0   = O_HE1   + (size_t)BB*K2H;
constexpr size_t O_HM1   = O_HM0   + (size_t)BB*K2H;
constexpr size_t O_WTWHO = O_HM1   + (size_t)BB*K2H;
constexpr size_t O_LAB   = O_WTWHO + (size_t)BB*K2H;
constexpr size_t O_PART  = O_LAB   + 1024;
constexpr size_t O_BSPI  = O_PART  + (size_t)BB*16;
constexpr size_t O_BTGI  = O_BSPI  + H4;
constexpr size_t O_BMDI  = O_BTGI  + H4;
constexpr size_t O_WTGCI = O_BMDI  + H4;
// fp16 regions (sizes in float slots = halves/2)
constexpr size_t O_INP16 = O_WTGCI + H4;
constexpr size_t O_MID216= O_INP16 + (size_t)BB*LEN*256;
constexpr size_t O_DEC16 = O_MID216+ (size_t)BB*LEN*256;
constexpr size_t O_XE16  = O_DEC16 + (size_t)BB*256;
constexpr size_t O_TU16  = O_XE16  + (size_t)BB*256;
constexpr size_t O_HT16A = O_TU16  + (size_t)BB*256;
constexpr size_t O_HT16B = O_HT16A + (size_t)BB*512;
constexpr size_t O_HE16A = O_HT16B + (size_t)BB*512;
constexpr size_t O_HE16B = O_HE16A + (size_t)BB*512;
constexpr size_t O_HM16A = O_HE16B + (size_t)BB*512;
constexpr size_t O_HM16B = O_HM16A + (size_t)BB*512;
constexpr size_t O_WI16  = O_HM16B + (size_t)BB*512;
constexpr size_t O_WE16  = O_WI16  + (size_t)512*256;
constexpr size_t O_VD16  = O_WE16  + (size_t)512*512;
constexpr size_t O_WX16  = O_VD16  + (size_t)512*256;
constexpr size_t O_WTWH16= O_WX16  + (size_t)512*256;
constexpr size_t O_SPIH  = O_WTWH16+ (size_t)1024*512;
constexpr size_t O_SPHH  = O_SPIH  + (size_t)H4*256;
constexpr size_t O_TGX   = O_SPHH  + (size_t)H4*256;
constexpr size_t O_TGHH  = O_TGX   + (size_t)H4*256;
constexpr size_t O_MDIH  = O_TGHH  + (size_t)H4*256;
constexpr size_t O_MDHH  = O_MDIH  + (size_t)H4*256;
constexpr size_t G_TOTAL = O_MDHH  + (size_t)H4*256;

__device__ float g_buf[G_TOTAL];
__device__ __align__(128) unsigned g_arr[NSUB * 32];
__device__ unsigned g_master;
__device__ unsigned g_rel;

__device__ __forceinline__ void gsync(unsigned ph)
{
    __syncthreads();
    if (threadIdx.x == 0) {
        __threadfence();
        const unsigned sub = blockIdx.x & (NSUB - 1);
        const unsigned v = atomicAdd(&g_arr[sub * 32], 1u) + 1u;
        if (v == ph * (unsigned)SUBCNT) {
            const unsigned m = atomicAdd(&g_master, 1u) + 1u;
            if (m == ph * (unsigned)NSUB) atomicExch(&g_rel, ph);
        }
        while (*(volatile unsigned*)&g_rel < ph) { __nanosleep(32); }
        __threadfence();
    }
    __syncthreads();
}

__device__ __forceinline__ uint32_t s2u(const void* p)
{ uint32_t a; asm("{ .reg .u64 t; cvta.to.shared.u64 t, %1; cvt.u32.u64 %0, t; }" : "=r"(a) : "l"(p)); return a; }

__device__ __forceinline__ void mma_f16(float* d,
    uint32_t a0, uint32_t a1, uint32_t a2, uint32_t a3, uint32_t b0, uint32_t b1)
{
    asm volatile(
        "mma.sync.aligned.m16n8k16.row.col.f32.f16.f16.f32 "
        "{%0,%1,%2,%3},{%4,%5,%6,%7},{%8,%9},{%0,%1,%2,%3};"
        : "+f"(d[0]), "+f"(d[1]), "+f"(d[2]), "+f"(d[3])
        : "r"(a0), "r"(a1), "r"(a2), "r"(a3), "r"(b0), "r"(b1));
}

struct Params {
    const float *inp;
    const float *Wi_b, *Vd_b, *Wx_b, *V_w, *V_b, *reg_w, *reg_b;
    float* out; float* gb;
};

// issue one chunk (A 64B + B 64B per thread) as one cp.async group
__device__ __forceinline__ void cpAB(uint32_t sb, int buf, int srow, int shalf,
    const uint16_t* Ap, int Alda, int m0,
    const uint16_t* Wp, int Wld, int n0, int ko)
{
    const uint16_t* ar = Ap + (size_t)(m0 + srow) * Alda + ko + shalf * 32;
    const uint16_t* wr = Wp + (size_t)(n0 + srow) * Wld + ko + shalf * 32;
    const uint32_t da = sb + ((buf * 64 + srow) * PADU + shalf * 16) * 4;
    const uint32_t db = da + ABUFS * 4;
    asm volatile(
        "cp.async.ca.shared.global [%0],[%8],16;\n\t"
        "cp.async.ca.shared.global [%1],[%9],16;\n\t"
        "cp.async.ca.shared.global [%2],[%10],16;\n\t"
        "cp.async.ca.shared.global [%3],[%11],16;\n\t"
        "cp.async.ca.shared.global [%4],[%12],16;\n\t"
        "cp.async.ca.shared.global [%5],[%13],16;\n\t"
        "cp.async.ca.shared.global [%6],[%14],16;\n\t"
        "cp.async.ca.shared.global [%7],[%15],16;\n\t"
        "cp.async.commit_group;"
        :: "r"(da), "r"(da+16), "r"(da+32), "r"(da+48),
           "r"(db), "r"(db+16), "r"(db+32), "r"(db+48),
           "l"(ar), "l"(ar+8), "l"(ar+16), "l"(ar+24),
           "l"(wr), "l"(wr+8), "l"(wr+16), "l"(wr+24) : "memory");
}

// modes: 0 fp32 store; 1 tanh->fp16; 2 fused LSTM; 3 exp: xe16 + partial sums
__device__ void gemm16(
    const uint16_t* A1, int lda1, const uint16_t* W1, int K1,
    const uint16_t* A2, int lda2, const uint16_t* W2, int K2,
    const float* bias, const float* add1, int ld1, const float* add2, int ld2,
    const float* r1u, const float* r1v,
    const float* cin, const float* invp,
    const float* xsrc, int xld,
    float* out32, uint16_t* out16,
    float* hout32, uint16_t* hout16, int hstride,
    int M, int N, int mode,
    uint32_t* dsm, int vbid, int vgrid)
{
    const int tid = threadIdx.x, wid = tid >> 5, lane = tid & 31;
    const int g = lane >> 2, c4 = lane & 3;
    const int wm = (wid >> 1) << 5, wn = (wid & 1) << 5;
    const int srow = tid >> 1, shalf = tid & 1;
    const int NC = (K1 + K2) >> 6, k1c = K1 >> 6;
    const int nct = N >> 6, ntiles = (M >> 6) * nct;
    const uint32_t sb = s2u(dsm);
    const uint32_t* Bb = dsm + ABUFS;

    for (int t = vbid; t < ntiles; t += vgrid) {
        const int m0 = (t / nct) << 6, n0 = (t % nct) << 6;

        float sc4[4] = {1.f, 1.f, 1.f, 1.f};
        if (invp) {
#pragma unroll
            for (int r = 0; r < 4; r++) {
                const int row = m0 + wm + ((r >> 1) << 4) + ((r & 1) << 3) + g;
                float s = 0.f;
#pragma unroll
                for (int q = 0; q < 16; q++) s += invp[row * 16 + q];
                sc4[r] = 1.f / s;
            }
        }

        float acc[2][4][4];
#pragma unroll
        for (int i = 0; i < 2; i++)
#pragma unroll
            for (int j = 0; j < 4; j++)
#pragma unroll
                for (int q = 0; q < 4; q++) acc[i][j][q] = 0.f;

#pragma unroll
        for (int s = 0; s < 3; s++) {
            const int kb = s << 6;
            if (kb < K1) cpAB(sb, s, srow, shalf, A1, lda1, m0, W1, K1, n0, kb);
            else         cpAB(sb, s, srow, shalf, A2, lda2, m0, W2, K2, n0, kb - K1);
        }

        for (int c = 0; c < NC; c++) {
            asm volatile("cp.async.wait_group 2;" ::: "memory");
            __syncthreads();
            const int cn = c + 3;
            if (cn < NC) {
                const int kb = cn << 6;
                if (kb < K1) cpAB(sb, cn & 3, srow, shalf, A1, lda1, m0, W1, K1, n0, kb);
                else         cpAB(sb, cn & 3, srow, shalf, A2, lda2, m0, W2, K2, n0, kb - K1);
            }
            const int b = c & 3;
#pragma unroll
            for (int ks = 0; ks < 4; ks++) {
                uint32_t af[2][4], bf[4][2];
#pragma unroll
                for (int mf = 0; mf < 2; mf++) {
                    const int row = wm + (mf << 4) + g;
                    const uint32_t* ab = dsm + (b * 64 + row) * PADU + ks * 8;
                    const uint32_t* ab8 = dsm + (b * 64 + row + 8) * PADU + ks * 8;
                    af[mf][0] = ab[c4];   af[mf][1] = ab8[c4];
                    af[mf][2] = ab[c4+4]; af[mf][3] = ab8[c4+4];
                }
#pragma unroll
                for (int nf = 0; nf < 4; nf++) {
                    const int r = wn + (nf << 3) + g;
                    const uint32_t* bb = Bb + (b * 64 + r) * PADU + ks * 8;
                    bf[nf][0] = bb[c4]; bf[nf][1] = bb[c4 + 4];
                }
#pragma unroll
                for (int mf = 0; mf < 2; mf++)
#pragma unroll
                    for (int nf = 0; nf < 4; nf++)
                        mma_f16(acc[mf][nf], af[mf][0], af[mf][1], af[mf][2], af[mf][3],
                                bf[nf][0], bf[nf][1]);
            }
            if (invp && c == k1c - 1) {
#pragma unroll
                for (int mf = 0; mf < 2; mf++)
#pragma unroll
                    for (int nf = 0; nf < 4; nf++) {
                        acc[mf][nf][0] *= sc4[mf*2];   acc[mf][nf][1] *= sc4[mf*2];
                        acc[mf][nf][2] *= sc4[mf*2+1]; acc[mf][nf][3] *= sc4[mf*2+1];
                    }
            }
        }

        const int mA0 = m0 + wm, nb0 = n0 + wn;
#pragma unroll
        for (int mf = 0; mf < 2; mf++) {
            const int mA = mA0 + (mf << 4) + g, mB = mA + 8;
            if (mode == 0) {
#pragma unroll
                for (int nf = 0; nf < 4; nf++) {
                    const int nc = nb0 + (nf << 3) + (c4 << 1);
                    float x0 = acc[mf][nf][0], x1 = acc[mf][nf][1];
                    float x2 = acc[mf][nf][2], x3 = acc[mf][nf][3];
                    if (bias) { x0 += bias[nc]; x1 += bias[nc+1]; x2 += bias[nc]; x3 += bias[nc+1]; }
                    *(float2*)(out32 + (size_t)mA * N + nc) = make_float2(x0, x1);
                    *(float2*)(out32 + (size_t)mB * N + nc) = make_float2(x2, x3);
                }
            } else if (mode == 1) {
#pragma unroll
                for (int nf = 0; nf < 4; nf++) {
                    const int nc = nb0 + (nf << 3) + (c4 << 1);
                    float x0 = acc[mf][nf][0], x1 = acc[mf][nf][1];
                    float x2 = acc[mf][nf][2], x3 = acc[mf][nf][3];
                    x0 += add1[(size_t)mA*ld1+nc]; x1 += add1[(size_t)mA*ld1+nc+1];
                    x2 += add1[(size_t)mB*ld1+nc]; x3 += add1[(size_t)mB*ld1+nc+1];
                    x0 += add2[(size_t)mA*ld2+nc]; x1 += add2[(size_t)mA*ld2+nc+1];
                    x2 += add2[(size_t)mB*ld2+nc]; x3 += add2[(size_t)mB*ld2+nc+1];
                    __half2 hA = __floats2half2_rn(tanhf(x0), tanhf(x1));
                    __half2 hB = __floats2half2_rn(tanhf(x2), tanhf(x3));
                    *(uint32_t*)(out16 + (size_t)mA * N + nc) = *(uint32_t*)&hA;
                    *(uint32_t*)(out16 + (size_t)mB * N + nc) = *(uint32_t*)&hB;
                }
            } else if (mode == 3) {
                float sA = 0.f, sB = 0.f;
#pragma unroll
                for (int nf = 0; nf < 4; nf++) {
                    const int nc = nb0 + (nf << 3) + (c4 << 1);
                    float e0 = expf(acc[mf][nf][0] + bias[nc]);
                    float e1 = expf(acc[mf][nf][1] + bias[nc+1]);
                    float e2 = expf(acc[mf][nf][2] + bias[nc]);
                    float e3 = expf(acc[mf][nf][3] + bias[nc+1]);
                    sA += e0 + e1; sB += e2 + e3;
                    float2 xa = *(const float2*)(xsrc + (size_t)mA * xld + nc);
                    float2 xb = *(const float2*)(xsrc + (size_t)mB * xld + nc);
                    __half2 hA = __floats2half2_rn(xa.x * e0, xa.y * e1);
                    __half2 hB = __floats2half2_rn(xb.x * e2, xb.y * e3);
                    *(uint32_t*)(out16 + (size_t)mA * 512 + nc) = *(uint32_t*)&hA;
                    *(uint32_t*)(out16 + (size_t)mB * 512 + nc) = *(uint32_t*)&hB;
                }
                sA += __shfl_xor_sync(0xffffffffu, sA, 1);
                sA += __shfl_xor_sync(0xffffffffu, sA, 2);
                sB += __shfl_xor_sync(0xffffffffu, sB, 1);
                sB += __shfl_xor_sync(0xffffffffu, sB, 2);
                if (c4 == 0) {
                    out32[mA * 16 + (nb0 >> 5)] = sA;
                    out32[mB * 16 + (nb0 >> 5)] = sB;
                }
            } else {
                const float ra = r1u ? r1u[mA] : 0.f, rb = r1u ? r1u[mB] : 0.f;
#pragma unroll
                for (int nf = 0; nf < 4; nf++) {
                    const int nc = nb0 + (nf << 3) + (c4 << 1);
                    float v00 = acc[mf][nf][0] + bias[nc], v01 = acc[mf][nf][1] + bias[nc+1];
                    float v10 = acc[mf][nf][2] + bias[nc], v11 = acc[mf][nf][3] + bias[nc+1];
                    if (r1u) {
                        v00 += ra * r1v[nc]; v01 += ra * r1v[nc+1];
                        v10 += rb * r1v[nc]; v11 += rb * r1v[nc+1];
                    }
                    const float t00 = __shfl_xor_sync(0xffffffffu, v00, 1);
                    const float t01 = __shfl_xor_sync(0xffffffffu, v01, 1);
                    const float t10 = __shfl_xor_sync(0xffffffffu, v10, 1);
                    const float t11 = __shfl_xor_sync(0xffffffffu, v11, 1);
                    int m; float fi, ff, fg, fo;
                    if ((c4 & 1) == 0) { m = mA; fi = v00; ff = v01; fg = t00; fo = t01; }
                    else               { m = mB; fi = t10; ff = t11; fg = v10; fo = v11; }
                    const int h = ((nb0 + (nf << 3)) >> 2) + (c4 >> 1);
                    const float cold = cin[(size_t)m * 1024 + 512 + h];
                    const float si = 1.f / (1.f + expf(-fi));
                    const float sf = 1.f / (1.f + expf(-ff));
                    const float so = 1.f / (1.f + expf(-fo));
                    const float c2 = sf * cold + si * tanhf(fg);
                    const float hn = so * tanhf(c2);
                    out32[(size_t)m * 1024 + h] = hn;
                    out32[(size_t)m * 1024 + 512 + h] = c2;
                    out16[(size_t)m * 1024 + h] = __half_as_ushort(__float2half_rn(hn));
                    out16[(size_t)m * 1024 + 512 + h] = __half_as_ushort(__float2half_rn(c2));
                    if (hout32) {
                        hout32[(size_t)m * hstride + h] = hn;
                        hout16[(size_t)m * hstride + h] = __half_as_ushort(__float2half_rn(hn));
                    }
                }
            }
        }
        __syncthreads();
    }
}

__global__ __launch_bounds__(NTHR) void mega(Params p)
{
    extern __shared__ uint32_t dsm[];
    __shared__ float ssc[LEN];
    const int tid = threadIdx.x, wid = tid >> 5, lane = tid & 31;

    float* gb = p.gb;
    float* wiseq = gb + O_WISEQ;  float* mid2 = gb + O_MID2;  float* ybuf = gb + O_Y;
    float* ht0 = gb + O_HT0;  float* ht1 = gb + O_HT1;
    float* he0 = gb + O_HE0;  float* he1 = gb + O_HE1;
    float* hm0 = gb + O_HM0;  float* hm1 = gb + O_HM1;
    float* wtwho = gb + O_WTWHO;  float* lab = gb + O_LAB;  float* part = gb + O_PART;
    float* bspi = gb + O_BSPI;  float* btgi = gb + O_BTGI;
    float* bmdi = gb + O_BMDI;  float* wtgci = gb + O_WTGCI;
    uint16_t* INP16 = (uint16_t*)(gb + O_INP16);
    uint16_t* MID216 = (uint16_t*)(gb + O_MID216);
    uint16_t* DEC16 = (uint16_t*)(gb + O_DEC16);
    uint16_t* XE16 = (uint16_t*)(gb + O_XE16);
    uint16_t* TU16 = (uint16_t*)(gb + O_TU16);
    uint16_t* HT16[2] = {(uint16_t*)(gb + O_HT16A), (uint16_t*)(gb + O_HT16B)};
    uint16_t* HE16[2] = {(uint16_t*)(gb + O_HE16A), (uint16_t*)(gb + O_HE16B)};
    uint16_t* HM16[2] = {(uint16_t*)(gb + O_HM16A), (uint16_t*)(gb + O_HM16B)};
    const uint16_t* WI16 = (const uint16_t*)(gb + O_WI16);
    const uint16_t* WE16 = (const uint16_t*)(gb + O_WE16);
    const uint16_t* VD16 = (const uint16_t*)(gb + O_VD16);
    const uint16_t* WX16 = (const uint16_t*)(gb + O_WX16);
    const uint16_t* WTWH16 = (const uint16_t*)(gb + O_WTWH16);
    const uint16_t* SPIH = (const uint16_t*)(gb + O_SPIH);
    const uint16_t* SPHH = (const uint16_t*)(gb + O_SPHH);
    const uint16_t* TGX = (const uint16_t*)(gb + O_TGX);
    const uint16_t* TGHH = (const uint16_t*)(gb + O_TGHH);
    const uint16_t* MDIH = (const uint16_t*)(gb + O_MDIH);
    const uint16_t* MDHH = (const uint16_t*)(gb + O_MDHH);

    unsigned ph = 0;

    gemm16(INP16, 512, WI16, 512, nullptr, 0, nullptr, 0, p.Wi_b,
           nullptr, 0, nullptr, 0, nullptr, nullptr, nullptr, nullptr, nullptr, 0,
           wiseq, nullptr, nullptr, nullptr, 0, BB*LEN, HH, 0, dsm, blockIdx.x, NBLK);
    gsync(++ph);

    for (int k = 0; k < LOOKN; k++) {
        const int kb = k & 1;
        float* htin32  = kb ? ht1 : ht0;
        float* htout32 = kb ? ht0 : ht1;
        uint16_t* htin16  = HT16[kb];
        uint16_t* htout16 = HT16[kb ^ 1];

        gemm16(DEC16, 512, TGX, 512, htin16, 1024, TGHH, 512, btgi,
               nullptr, 0, nullptr, 0, lab, wtgci, htin32, nullptr, nullptr, 0,
               htout32, htout16, nullptr, nullptr, 0, BB, H4, 2, dsm, blockIdx.x, NBLK);
        gsync(++ph);

        if (blockIdx.x < 64) {
            gemm16(htout16, 1024, WTWH16, K2H, nullptr, 0, nullptr, 0, nullptr,
                   nullptr, 0, nullptr, 0, nullptr, nullptr, nullptr, nullptr, nullptr, 0,
                   wtwho, nullptr, nullptr, nullptr, 0, BB, K2H, 0, dsm, blockIdx.x, 64);
        } else if (blockIdx.x == 64) {
            for (int r = wid; r < BB; r += 4) {
                float s = 0.f;
                for (int h = lane; h < HH; h += 32) s += htout32[(size_t)r * K2H + h] * p.reg_w[h];
#pragma unroll
                for (int o = 16; o; o >>= 1) s += __shfl_xor_sync(0xffffffffu, s, o);
                if (lane == 0) { const float tv = s + p.reg_b[0]; p.out[r * LOOKN + k] = tv; lab[r] = tv; }
            }
        } else {
            const int base = (blockIdx.x - 65) * NTHR + tid;
            for (int i = base; i < BB * K2H; i += (NBLK - 65) * NTHR) {
                he0[i] = 0.f; hm0[i] = 0.f;
                ((uint32_t*)HE16[0])[i >> 1] = 0u; ((uint32_t*)HM16[0])[i >> 1] = 0u;
            }
        }
        gsync(++ph);

        // prologue: tu(0), sc(0)
        gemm16(HE16[0], 1024, WE16, K2H, nullptr, 0, nullptr, 0, nullptr,
               wiseq, LEN * HH, wtwho, K2H, nullptr, nullptr, nullptr, nullptr, nullptr, 0,
               nullptr, TU16, nullptr, nullptr, 0, BB, HH, 1, dsm, blockIdx.x, NBLK);
        gsync(++ph);
        gemm16(TU16, 512, VD16, 512, nullptr, 0, nullptr, 0, p.Vd_b,
               nullptr, 0, nullptr, 0, nullptr, nullptr, nullptr, nullptr,
               p.inp, LEN * 512,
               part, XE16, nullptr, nullptr, 0, BB, HH, 3, dsm, blockIdx.x, NBLK);
        gsync(++ph);

        for (int l = 0; l < LEN; l++) {
            const int lb = l & 1;
            float* hein32  = lb ? he1 : he0;
            float* heout32 = lb ? he0 : he1;
            float* hmin32  = lb ? hm1 : hm0;
            float* hmout32 = lb ? hm0 : hm1;
            uint16_t* hein16 = HE16[lb], *heout16 = HE16[lb ^ 1];
            uint16_t* hmin16 = HM16[lb], *hmout16 = HM16[lb ^ 1];

            // sp(l): seg1 acc scaled by softmax inv
            gemm16(XE16, 512, SPIH, 512, hein16, 1024, SPHH, 512, bspi,
                   nullptr, 0, nullptr, 0, nullptr, nullptr, hein32, part, nullptr, 0,
                   heout32, heout16, nullptr, nullptr, 0, BB, H4, 2, dsm, blockIdx.x, NBLK);
            gsync(++ph);

            // mid(l) || tu(l+1)
            if (blockIdx.x < 160) {
                gemm16(heout16, 1024, MDIH, 512, hmin16, 1024, MDHH, 512, bmdi,
                       nullptr, 0, nullptr, 0, nullptr, nullptr, hmin32, nullptr, nullptr, 0,
                       hmout32, hmout16, mid2 + (size_t)l * HH, MID216 + (size_t)l * HH, LEN * HH,
                       BB, H4, 2, dsm, blockIdx.x, 160);
            } else if (l < LEN - 1) {
                gemm16(heout16, 1024, WE16, K2H, nullptr, 0, nullptr, 0, nullptr,
                       wiseq + (size_t)(l + 1) * HH, LEN * HH, wtwho, K2H,
                       nullptr, nullptr, nullptr, nullptr, nullptr, 0,
                       nullptr, TU16, nullptr, nullptr, 0, BB, HH, 1, dsm, blockIdx.x - 160, 136);
            }
            gsync(++ph);

            if (l < LEN - 1) {
                gemm16(TU16, 512, VD16, 512, nullptr, 0, nullptr, 0, p.Vd_b,
                       nullptr, 0, nullptr, 0, nullptr, nullptr, nullptr, nullptr,
                       p.inp + (size_t)(l + 1) * 512, LEN * 512,
                       part, XE16, nullptr, nullptr, 0, BB, HH, 3, dsm, blockIdx.x, NBLK);
                gsync(++ph);
            }
        }

        gemm16(MID216, 512, WX16, 512, nullptr, 0, nullptr, 0, p.Wx_b,
               nullptr, 0, nullptr, 0, nullptr, nullptr, nullptr, nullptr, nullptr, 0,
               ybuf, nullptr, nullptr, nullptr, 0, BB * LEN, HH, 0, dsm, blockIdx.x, NBLK);
        gsync(++ph);

        if (blockIdx.x < BB) {
            const int b = blockIdx.x;
            for (int l = wid; l < LEN; l += 4) {
                const float* yr = ybuf + ((size_t)b * LEN + l) * HH;
                float pv = 0.f;
                for (int h = lane; h < HH; h += 32)
                    pv += tanhf(wtwho[(size_t)b * K2H + 512 + h] + yr[h]) * p.V_w[h];
#pragma unroll
                for (int o = 16; o; o >>= 1) pv += __shfl_xor_sync(0xffffffffu, pv, o);
                if (lane == 0) ssc[l] = pv + p.V_b[0];
            }
            __syncthreads();
            float a0 = 0.f, a1 = 0.f, a2 = 0.f, a3 = 0.f;
            for (int l = 0; l < LEN; l++) {
                const float s = ssc[l];
                const float* mr = mid2 + ((size_t)b * LEN + l) * HH;
                a0 += s * mr[tid];       a1 += s * mr[tid + 128];
                a2 += s * mr[tid + 256]; a3 += s * mr[tid + 384];
            }
            DEC16[(size_t)b * 512 + tid]       = __half_as_ushort(__float2half_rn(a0));
            DEC16[(size_t)b * 512 + tid + 128] = __half_as_ushort(__float2half_rn(a1));
            DEC16[(size_t)b * 512 + tid + 256] = __half_as_ushort(__float2half_rn(a2));
            DEC16[(size_t)b * 512 + tid + 384] = __half_as_ushort(__float2half_rn(a3));
        }
        gsync(++ph);
    }
}

__global__ __launch_bounds__(256) void prep_k(
    const float* bihsp, const float* bhhsp, const float* bihtg, const float* bhhtg,
    const float* bihmid, const float* bhhmid, const float* wihtg,
    const float* wtw, const float* whw,
    const float* wisp, const float* whsp, const float* whtg,
    const float* wimd, const float* whmd,
    const float* wiw, const float* wew, const float* vdw, const float* wxw,
    const float* inp)
{
    const int nt = gridDim.x * 256;
    const int gid = blockIdx.x * 256 + threadIdx.x;
    __half* WI16 = (__half*)(g_buf + O_WI16);
    __half* WE16 = (__half*)(g_buf + O_WE16);
    __half* VD16 = (__half*)(g_buf + O_VD16);
    __half* WX16 = (__half*)(g_buf + O_WX16);
    __half* WTWH16 = (__half*)(g_buf + O_WTWH16);
    __half* SPIH = (__half*)(g_buf + O_SPIH);
    __half* SPHH = (__half*)(g_buf + O_SPHH);
    __half* TGX = (__half*)(g_buf + O_TGX);
    __half* TGHH = (__half*)(g_buf + O_TGHH);
    __half* MDIH = (__half*)(g_buf + O_MDIH);
    __half* MDHH = (__half*)(g_buf + O_MDHH);
    __half* INP16 = (__half*)(g_buf + O_INP16);

    for (int i = gid; i < 512*512; i += nt) {
        WI16[i] = __float2half_rn(wiw[i]);
        VD16[i] = __float2half_rn(vdw[i]);
        WX16[i] = __float2half_rn(wxw[i]);
    }
    for (int i = gid; i < 512*1024; i += nt) WE16[i] = __float2half_rn(wew[i]);
    for (int i = gid; i < 1024*1024; i += nt) {
        const int r = i >> 10, c = i & 1023;
        WTWH16[i] = __float2half_rn(r < 512 ? wtw[(size_t)r*1024 + c] : whw[(size_t)(r-512)*1024 + c]);
    }
    for (int i = gid; i < BB*LEN*512; i += nt) INP16[i] = __float2half_rn(inp[i]);
    for (int i = gid; i < H4*512; i += nt) {
        const int rp = i >> 9, kk = i & 511;
        const int h = rp >> 2, gg = rp & 3;
        const size_t src = (size_t)(gg * 512 + h);
        SPIH[i] = __float2half_rn(wisp[src*512 + kk]);
        SPHH[i] = __float2half_rn(whsp[src*512 + kk]);
        TGHH[i] = __float2half_rn(whtg[src*512 + kk]);
        MDIH[i] = __float2half_rn(wimd[src*512 + kk]);
        MDHH[i] = __float2half_rn(whmd[src*512 + kk]);
        TGX[i]  = __float2half_rn(wihtg[src*513 + 1 + kk]);
    }
    for (int i = gid; i < H4; i += nt) {
        const int h = i >> 2, gg = i & 3;
        const int s = gg * 512 + h;
        g_buf[O_BSPI + i]  = bihsp[s] + bhhsp[s];
        g_buf[O_BTGI + i]  = bihtg[s] + bhhtg[s];
        g_buf[O_BMDI + i]  = bihmid[s] + bhhmid[s];
        g_buf[O_WTGCI + i] = wihtg[(size_t)s * 513];
    }
}

__global__ __launch_bounds__(256) void init_k(const float* __restrict__ labp)
{
    const int i = blockIdx.x * 256 + threadIdx.x;
    if (i < NSUB) g_arr[i * 32] = 0u;
    if (i == NSUB) g_master = 0u;
    if (i == NSUB + 1) g_rel = 0u;
    if (i < BB * K2H) {
        g_buf[O_HT0 + i] = 0.f;
        ((uint16_t*)(g_buf + O_HT16A))[i] = 0;
    }
    if (i < BB * HH) ((uint16_t*)(g_buf + O_DEC16))[i] = 0;
    if (i < BB) g_buf[O_LAB + i] = labp[(size_t)i * LABW + STARTI];
}

extern "C" void kernel_launch(void* const* d_in, const int* in_sizes, int n_in,
                              void* d_out, int out_size)
{
    Params p;
    p.inp   = (const float*)d_in[0];
    p.Wi_b  = (const float*)d_in[15];
    p.Vd_b  = (const float*)d_in[19];
    p.Wx_b  = (const float*)d_in[21];
    p.V_w   = (const float*)d_in[23];
    p.V_b   = (const float*)d_in[24];
    p.reg_w = (const float*)d_in[25];
    p.reg_b = (const float*)d_in[26];
    p.out   = (float*)d_out;

    float* gb = nullptr;
    cudaGetSymbolAddress((void**)&gb, g_buf);
    p.gb = gb;

    cudaFuncSetAttribute(mega, cudaFuncAttributeMaxDynamicSharedMemorySize, SMEMB);

    prep_k<<<2048, 256>>>(
        (const float*)d_in[4], (const float*)d_in[5], (const float*)d_in[8],
        (const float*)d_in[9], (const float*)d_in[12], (const float*)d_in[13],
        (const float*)d_in[6], (const float*)d_in[17], (const float*)d_in[22],
        (const float*)d_in[2], (const float*)d_in[3], (const float*)d_in[7],
        (const float*)d_in[10], (const float*)d_in[11],
        (const float*)d_in[14], (const float*)d_in[16],
        (const float*)d_in[18], (const float*)d_in[20],
        (const float*)d_in[0]);
    init_k<<<(BB * K2H + 255) / 256, 256>>>((const float*)d_in[1]);
    mega<<<NBLK, NTHR, SMEMB>>>(p);
}

// round 15
// speedup vs baseline: 2.7112x; 1.2203x over previous
#include <cuda_runtime.h>
#include <cuda_fp16.h>
#include <math.h>
#include <stdint.h>

#define BB 256
#define HH 512
#define H4 2048
#define LEN 48
#define LOOKN 10
#define K2H 1024
#define STARTI 48
#define LABW 58
#define NBLK 296
#define NTHR 256
#define NSUB 8
#define SUBCNT 37
#define PADU 36
#define ABUFS (4*64*PADU)
#define SMEMB (2*ABUFS*4)

// ---- scratch layout (float slots; fp16 data packed 2/slot) ----
constexpr size_t O_WISEQ = 0;
constexpr size_t O_MID2  = O_WISEQ + (size_t)BB*LEN*HH;
constexpr size_t O_Y     = O_MID2  + (size_t)BB*LEN*HH;
constexpr size_t O_HT0   = O_Y     + (size_t)BB*LEN*HH;
constexpr size_t O_HT1   = O_HT0   + (size_t)BB*K2H;
constexpr size_t O_HE0   = O_HT1   + (size_t)BB*K2H;
constexpr size_t O_HE1   = O_HE0   + (size_t)BB*K2H;
constexpr size_t O_HM0   = O_HE1   + (size_t)BB*K2H;
constexpr size_t O_HM1   = O_HM0   + (size_t)BB*K2H;
constexpr size_t O_WTWHO = O_HM1   + (size_t)BB*K2H;
constexpr size_t O_LAB   = O_WTWHO + (size_t)BB*K2H;
constexpr size_t O_PART  = O_LAB   + 1024;
constexpr size_t O_BSPI  = O_PART  + (size_t)BB*16;
constexpr size_t O_BTGI  = O_BSPI  + H4;
constexpr size_t O_BMDI  = O_BTGI  + H4;
constexpr size_t O_WTGCI = O_BMDI  + H4;
constexpr size_t O_INP16 = O_WTGCI + H4;
constexpr size_t O_MID216= O_INP16 + (size_t)BB*LEN*256;
constexpr size_t O_DEC16 = O_MID216+ (size_t)BB*LEN*256;
constexpr size_t O_XE16  = O_DEC16 + (size_t)BB*256;
constexpr size_t O_TU16  = O_XE16  + (size_t)BB*256;
constexpr size_t O_HT16A = O_TU16  + (size_t)BB*256;
constexpr size_t O_HT16B = O_HT16A + (size_t)BB*512;
constexpr size_t O_HE16A = O_HT16B + (size_t)BB*512;
constexpr size_t O_HE16B = O_HE16A + (size_t)BB*512;
constexpr size_t O_HM16A = O_HE16B + (size_t)BB*512;
constexpr size_t O_HM16B = O_HM16A + (size_t)BB*512;
constexpr size_t O_WI16  = O_HM16B + (size_t)BB*512;
constexpr size_t O_WE16  = O_WI16  + (size_t)512*256;
constexpr size_t O_VD16  = O_WE16  + (size_t)512*512;
constexpr size_t O_WX16  = O_VD16  + (size_t)512*256;
constexpr size_t O_WTWH16= O_WX16  + (size_t)512*256;
constexpr size_t O_SPIH  = O_WTWH16+ (size_t)1024*512;
constexpr size_t O_SPHH  = O_SPIH  + (size_t)H4*256;
constexpr size_t O_TGX   = O_SPHH  + (size_t)H4*256;
constexpr size_t O_TGHH  = O_TGX   + (size_t)H4*256;
constexpr size_t O_MDIH  = O_TGHH  + (size_t)H4*256;
constexpr size_t O_MDHH  = O_MDIH  + (size_t)H4*256;
constexpr size_t G_TOTAL = O_MDHH  + (size_t)H4*256;

__device__ float g_buf[G_TOTAL];
__device__ __align__(128) unsigned g_arr[NSUB * 32];
__device__ unsigned g_master;
__device__ unsigned g_rel;

__device__ __forceinline__ void gsync(unsigned ph)
{
    __syncthreads();
    if (threadIdx.x == 0) {
        __threadfence();
        const unsigned sub = blockIdx.x & (NSUB - 1);
        const unsigned v = atomicAdd(&g_arr[sub * 32], 1u) + 1u;
        if (v == ph * (unsigned)SUBCNT) {
            const unsigned m = atomicAdd(&g_master, 1u) + 1u;
            if (m == ph * (unsigned)NSUB) atomicExch(&g_rel, ph);
        }
        while (*(volatile unsigned*)&g_rel < ph) { __nanosleep(32); }
        __threadfence();
    }
    __syncthreads();
}

__device__ __forceinline__ uint32_t s2u(const void* p)
{ uint32_t a; asm("{ .reg .u64 t; cvta.to.shared.u64 t, %1; cvt.u32.u64 %0, t; }" : "=r"(a) : "l"(p)); return a; }

__device__ __forceinline__ void mma_f16(float* d,
    uint32_t a0, uint32_t a1, uint32_t a2, uint32_t a3, uint32_t b0, uint32_t b1)
{
    asm volatile(
        "mma.sync.aligned.m16n8k16.row.col.f32.f16.f16.f32 "
        "{%0,%1,%2,%3},{%4,%5,%6,%7},{%8,%9},{%0,%1,%2,%3};"
        : "+f"(d[0]), "+f"(d[1]), "+f"(d[2]), "+f"(d[3])
        : "r"(a0), "r"(a1), "r"(a2), "r"(a3), "r"(b0), "r"(b1));
}

struct Params {
    const float *inp;
    const float *Wi_b, *Vd_b, *Wx_b, *V_w, *V_b, *reg_w, *reg_b;
    float* out; float* gb;
};

// one chunk: each of 256 threads stages 32B of A and 32B of B
__device__ __forceinline__ void cpAB(uint32_t sb, int buf, int srow, int sq,
    const uint16_t* Ap, int Alda, int m0,
    const uint16_t* Wp, int Wld, int n0, int ko)
{
    const uint16_t* ar = Ap + (size_t)(m0 + srow) * Alda + ko + sq * 16;
    const uint16_t* wr = Wp + (size_t)(n0 + srow) * Wld + ko + sq * 16;
    const uint32_t da = sb + ((buf * 64 + srow) * PADU + sq * 8) * 4;
    const uint32_t db = da + ABUFS * 4;
    asm volatile(
        "cp.async.ca.shared.global [%0],[%4],16;\n\t"
        "cp.async.ca.shared.global [%1],[%5],16;\n\t"
        "cp.async.ca.shared.global [%2],[%6],16;\n\t"
        "cp.async.ca.shared.global [%3],[%7],16;\n\t"
        "cp.async.commit_group;"
        :: "r"(da), "r"(da+16), "r"(db), "r"(db+16),
           "l"(ar), "l"(ar+8), "l"(wr), "l"(wr+8) : "memory");
}

// modes: 0 fp32 store; 1 tanh->fp16; 2 fused LSTM; 3 exp: xe16 + partial sums
__device__ void gemm16(
    const uint16_t* A1, int lda1, const uint16_t* W1, int K1,
    const uint16_t* A2, int lda2, const uint16_t* W2, int K2,
    const float* bias, const float* add1, int ld1, const float* add2, int ld2,
    const float* r1u, const float* r1v,
    const float* cin, const float* invp,
    const float* xsrc, int xld,
    float* out32, uint16_t* out16,
    float* hout32, uint16_t* hout16, int hstride,
    int M, int N, int mode,
    uint32_t* dsm, int vbid, int vgrid)
{
    const int tid = threadIdx.x, wid = tid >> 5, lane = tid & 31;
    const int g = lane >> 2, c4 = lane & 3;
    const int wm = (wid >> 1) << 4, wn = (wid & 1) << 5;
    const int srow = tid >> 2, sq = tid & 3;
    const int NC = (K1 + K2) >> 6, k1c = K1 >> 6;
    const int nct = N >> 6, ntiles = (M >> 6) * nct;
    const uint32_t sb = s2u(dsm);
    const uint32_t* Bb = dsm + ABUFS;

    for (int t = vbid; t < ntiles; t += vgrid) {
        const int m0 = (t / nct) << 6, n0 = (t % nct) << 6;

        float sc2[2] = {1.f, 1.f};
        if (invp) {
#pragma unroll
            for (int r = 0; r < 2; r++) {
                const int row = m0 + wm + (r << 3) + g;
                float s = 0.f;
#pragma unroll
                for (int q = 0; q < 16; q++) s += invp[row * 16 + q];
                sc2[r] = 1.f / s;
            }
        }

        float acc[4][4];
#pragma unroll
        for (int j = 0; j < 4; j++)
#pragma unroll
            for (int q = 0; q < 4; q++) acc[j][q] = 0.f;

#pragma unroll
        for (int s = 0; s < 3; s++) {
            const int kb = s << 6;
            if (kb < K1) cpAB(sb, s, srow, sq, A1, lda1, m0, W1, K1, n0, kb);
            else         cpAB(sb, s, srow, sq, A2, lda2, m0, W2, K2, n0, kb - K1);
        }

        for (int c = 0; c < NC; c++) {
            // tail-aware drain: guarantee chunk c complete before consuming it
            if (c < NC - 2)      asm volatile("cp.async.wait_group 2;" ::: "memory");
            else if (c == NC - 2) asm volatile("cp.async.wait_group 1;" ::: "memory");
            else                 asm volatile("cp.async.wait_group 0;" ::: "memory");
            __syncthreads();
            const int cn = c + 3;
            if (cn < NC) {
                const int kb = cn << 6;
                if (kb < K1) cpAB(sb, cn & 3, srow, sq, A1, lda1, m0, W1, K1, n0, kb);
                else         cpAB(sb, cn & 3, srow, sq, A2, lda2, m0, W2, K2, n0, kb - K1);
            }
            const int b = c & 3;
#pragma unroll
            for (int ks = 0; ks < 4; ks++) {
                uint32_t af[4], bf[4][2];
                {
                    const uint32_t* ab  = dsm + (b * 64 + wm + g) * PADU + ks * 8;
                    const uint32_t* ab8 = dsm + (b * 64 + wm + g + 8) * PADU + ks * 8;
                    af[0] = ab[c4];   af[1] = ab8[c4];
                    af[2] = ab[c4+4]; af[3] = ab8[c4+4];
                }
#pragma unroll
                for (int nf = 0; nf < 4; nf++) {
                    const int r = wn + (nf << 3) + g;
                    const uint32_t* bb = Bb + (b * 64 + r) * PADU + ks * 8;
                    bf[nf][0] = bb[c4]; bf[nf][1] = bb[c4 + 4];
                }
#pragma unroll
                for (int nf = 0; nf < 4; nf++)
                    mma_f16(acc[nf], af[0], af[1], af[2], af[3], bf[nf][0], bf[nf][1]);
            }
            if (invp && c == k1c - 1) {
#pragma unroll
                for (int nf = 0; nf < 4; nf++) {
                    acc[nf][0] *= sc2[0]; acc[nf][1] *= sc2[0];
                    acc[nf][2] *= sc2[1]; acc[nf][3] *= sc2[1];
                }
            }
        }

        const int mA = m0 + wm + g, mB = mA + 8;
        const int nb0 = n0 + wn;
        if (mode == 0) {
#pragma unroll
            for (int nf = 0; nf < 4; nf++) {
                const int nc = nb0 + (nf << 3) + (c4 << 1);
                float x0 = acc[nf][0], x1 = acc[nf][1];
                float x2 = acc[nf][2], x3 = acc[nf][3];
                if (bias) { x0 += bias[nc]; x1 += bias[nc+1]; x2 += bias[nc]; x3 += bias[nc+1]; }
                *(float2*)(out32 + (size_t)mA * N + nc) = make_float2(x0, x1);
                *(float2*)(out32 + (size_t)mB * N + nc) = make_float2(x2, x3);
            }
        } else if (mode == 1) {
#pragma unroll
            for (int nf = 0; nf < 4; nf++) {
                const int nc = nb0 + (nf << 3) + (c4 << 1);
                float x0 = acc[nf][0], x1 = acc[nf][1];
                float x2 = acc[nf][2], x3 = acc[nf][3];
                x0 += add1[(size_t)mA*ld1+nc]; x1 += add1[(size_t)mA*ld1+nc+1];
                x2 += add1[(size_t)mB*ld1+nc]; x3 += add1[(size_t)mB*ld1+nc+1];
                x0 += add2[(size_t)mA*ld2+nc]; x1 += add2[(size_t)mA*ld2+nc+1];
                x2 += add2[(size_t)mB*ld2+nc]; x3 += add2[(size_t)mB*ld2+nc+1];
                __half2 hA = __floats2half2_rn(tanhf(x0), tanhf(x1));
                __half2 hB = __floats2half2_rn(tanhf(x2), tanhf(x3));
                *(uint32_t*)(out16 + (size_t)mA * N + nc) = *(uint32_t*)&hA;
                *(uint32_t*)(out16 + (size_t)mB * N + nc) = *(uint32_t*)&hB;
            }
        } else if (mode == 3) {
            float sA = 0.f, sB = 0.f;
#pragma unroll
            for (int nf = 0; nf < 4; nf++) {
                const int nc = nb0 + (nf << 3) + (c4 << 1);
                float e0 = expf(acc[nf][0] + bias[nc]);
                float e1 = expf(acc[nf][1] + bias[nc+1]);
                float e2 = expf(acc[nf][2] + bias[nc]);
                float e3 = expf(acc[nf][3] + bias[nc+1]);
                sA += e0 + e1; sB += e2 + e3;
                float2 xa = *(const float2*)(xsrc + (size_t)mA * xld + nc);
                float2 xb = *(const float2*)(xsrc + (size_t)mB * xld + nc);
                __half2 hA = __floats2half2_rn(xa.x * e0, xa.y * e1);
                __half2 hB = __floats2half2_rn(xb.x * e2, xb.y * e3);
                *(uint32_t*)(out16 + (size_t)mA * 512 + nc) = *(uint32_t*)&hA;
                *(uint32_t*)(out16 + (size_t)mB * 512 + nc) = *(uint32_t*)&hB;
            }
            sA += __shfl_xor_sync(0xffffffffu, sA, 1);
            sA += __shfl_xor_sync(0xffffffffu, sA, 2);
            sB += __shfl_xor_sync(0xffffffffu, sB, 1);
            sB += __shfl_xor_sync(0xffffffffu, sB, 2);
            if (c4 == 0) {
                out32[mA * 16 + (nb0 >> 5)] = sA;
                out32[mB * 16 + (nb0 >> 5)] = sB;
            }
        } else {
            const float ra = r1u ? r1u[mA] : 0.f, rb = r1u ? r1u[mB] : 0.f;
#pragma unroll
            for (int nf = 0; nf < 4; nf++) {
                const int nc = nb0 + (nf << 3) + (c4 << 1);
                float v00 = acc[nf][0] + bias[nc], v01 = acc[nf][1] + bias[nc+1];
                float v10 = acc[nf][2] + bias[nc], v11 = acc[nf][3] + bias[nc+1];
                if (r1u) {
                    v00 += ra * r1v[nc]; v01 += ra * r1v[nc+1];
                    v10 += rb * r1v[nc]; v11 += rb * r1v[nc+1];
                }
                const float t00 = __shfl_xor_sync(0xffffffffu, v00, 1);
                const float t01 = __shfl_xor_sync(0xffffffffu, v01, 1);
                const float t10 = __shfl_xor_sync(0xffffffffu, v10, 1);
                const float t11 = __shfl_xor_sync(0xffffffffu, v11, 1);
                int m; float fi, ff, fg, fo;
                if ((c4 & 1) == 0) { m = mA; fi = v00; ff = v01; fg = t00; fo = t01; }
                else               { m = mB; fi = t10; ff = t11; fg = v10; fo = v11; }
                const int h = ((nb0 + (nf << 3)) >> 2) + (c4 >> 1);
                const float cold = cin[(size_t)m * 1024 + 512 + h];
                const float si = 1.f / (1.f + expf(-fi));
                const float sf = 1.f / (1.f + expf(-ff));
                const float so = 1.f / (1.f + expf(-fo));
                const float c2 = sf * cold + si * tanhf(fg);
                const float hn = so * tanhf(c2);
                out32[(size_t)m * 1024 + h] = hn;
                out32[(size_t)m * 1024 + 512 + h] = c2;
                out16[(size_t)m * 1024 + h] = __half_as_ushort(__float2half_rn(hn));
                out16[(size_t)m * 1024 + 512 + h] = __half_as_ushort(__float2half_rn(c2));
                if (hout32) {
                    hout32[(size_t)m * hstride + h] = hn;
                    hout16[(size_t)m * hstride + h] = __half_as_ushort(__float2half_rn(hn));
                }
            }
        }
        __syncthreads();
    }
}

__global__ __launch_bounds__(NTHR, 2) void mega(Params p)
{
    extern __shared__ uint32_t dsm[];
    __shared__ float ssc[LEN];
    const int tid = threadIdx.x, wid = tid >> 5, lane = tid & 31;

    float* gb = p.gb;
    float* wiseq = gb + O_WISEQ;  float* mid2 = gb + O_MID2;  float* ybuf = gb + O_Y;
    float* ht0 = gb + O_HT0;  float* ht1 = gb + O_HT1;
    float* he0 = gb + O_HE0;  float* hm0 = gb + O_HM0;
    float* he1 = gb + O_HE1;  float* hm1 = gb + O_HM1;
    float* wtwho = gb + O_WTWHO;  float* lab = gb + O_LAB;  float* part = gb + O_PART;
    float* bspi = gb + O_BSPI;  float* btgi = gb + O_BTGI;
    float* bmdi = gb + O_BMDI;  float* wtgci = gb + O_WTGCI;
    uint16_t* INP16 = (uint16_t*)(gb + O_INP16);
    uint16_t* MID216 = (uint16_t*)(gb + O_MID216);
    uint16_t* DEC16 = (uint16_t*)(gb + O_DEC16);
    uint16_t* XE16 = (uint16_t*)(gb + O_XE16);
    uint16_t* TU16 = (uint16_t*)(gb + O_TU16);
    uint16_t* HT16[2] = {(uint16_t*)(gb + O_HT16A), (uint16_t*)(gb + O_HT16B)};
    uint16_t* HE16[2] = {(uint16_t*)(gb + O_HE16A), (uint16_t*)(gb + O_HE16B)};
    uint16_t* HM16[2] = {(uint16_t*)(gb + O_HM16A), (uint16_t*)(gb + O_HM16B)};
    const uint16_t* WI16 = (const uint16_t*)(gb + O_WI16);
    const uint16_t* WE16 = (const uint16_t*)(gb + O_WE16);
    const uint16_t* VD16 = (const uint16_t*)(gb + O_VD16);
    const uint16_t* WX16 = (const uint16_t*)(gb + O_WX16);
    const uint16_t* WTWH16 = (const uint16_t*)(gb + O_WTWH16);
    const uint16_t* SPIH = (const uint16_t*)(gb + O_SPIH);
    const uint16_t* SPHH = (const uint16_t*)(gb + O_SPHH);
    const uint16_t* TGX = (const uint16_t*)(gb + O_TGX);
    const uint16_t* TGHH = (const uint16_t*)(gb + O_TGHH);
    const uint16_t* MDIH = (const uint16_t*)(gb + O_MDIH);
    const uint16_t* MDHH = (const uint16_t*)(gb + O_MDHH);

    unsigned ph = 0;

    gemm16(INP16, 512, WI16, 512, nullptr, 0, nullptr, 0, p.Wi_b,
           nullptr, 0, nullptr, 0, nullptr, nullptr, nullptr, nullptr, nullptr, 0,
           wiseq, nullptr, nullptr, nullptr, 0, BB*LEN, HH, 0, dsm, blockIdx.x, NBLK);
    gsync(++ph);

    for (int k = 0; k < LOOKN; k++) {
        const int kb = k & 1;
        float* htin32  = kb ? ht1 : ht0;
        float* htout32 = kb ? ht0 : ht1;
        uint16_t* htin16  = HT16[kb];
        uint16_t* htout16 = HT16[kb ^ 1];

        gemm16(DEC16, 512, TGX, 512, htin16, 1024, TGHH, 512, btgi,
               nullptr, 0, nullptr, 0, lab, wtgci, htin32, nullptr, nullptr, 0,
               htout32, htout16, nullptr, nullptr, 0, BB, H4, 2, dsm, blockIdx.x, NBLK);
        gsync(++ph);

        if (blockIdx.x < 64) {
            gemm16(htout16, 1024, WTWH16, K2H, nullptr, 0, nullptr, 0, nullptr,
                   nullptr, 0, nullptr, 0, nullptr, nullptr, nullptr, nullptr, nullptr, 0,
                   wtwho, nullptr, nullptr, nullptr, 0, BB, K2H, 0, dsm, blockIdx.x, 64);
        } else if (blockIdx.x == 64) {
            for (int r = wid; r < BB; r += 8) {
                float s = 0.f;
                for (int h = lane; h < HH; h += 32) s += htout32[(size_t)r * K2H + h] * p.reg_w[h];
#pragma unroll
                for (int o = 16; o; o >>= 1) s += __shfl_xor_sync(0xffffffffu, s, o);
                if (lane == 0) { const float tv = s + p.reg_b[0]; p.out[r * LOOKN + k] = tv; lab[r] = tv; }
            }
        } else {
            const int base = (blockIdx.x - 65) * NTHR + tid;
            for (int i = base; i < BB * K2H; i += (NBLK - 65) * NTHR) {
                he0[i] = 0.f; hm0[i] = 0.f;
                ((uint32_t*)HE16[0])[i >> 1] = 0u; ((uint32_t*)HM16[0])[i >> 1] = 0u;
            }
        }
        gsync(++ph);

        gemm16(HE16[0], 1024, WE16, K2H, nullptr, 0, nullptr, 0, nullptr,
               wiseq, LEN * HH, wtwho, K2H, nullptr, nullptr, nullptr, nullptr, nullptr, 0,
               nullptr, TU16, nullptr, nullptr, 0, BB, HH, 1, dsm, blockIdx.x, NBLK);
        gsync(++ph);
        gemm16(TU16, 512, VD16, 512, nullptr, 0, nullptr, 0, p.Vd_b,
               nullptr, 0, nullptr, 0, nullptr, nullptr, nullptr, nullptr,
               p.inp, LEN * 512,
               part, XE16, nullptr, nullptr, 0, BB, HH, 3, dsm, blockIdx.x, NBLK);
        gsync(++ph);

        for (int l = 0; l < LEN; l++) {
            const int lb = l & 1;
            float* hein32  = lb ? he1 : he0;
            float* heout32 = lb ? he0 : he1;
            float* hmin32  = lb ? hm1 : hm0;
            float* hmout32 = lb ? hm0 : hm1;
            uint16_t* hein16 = HE16[lb], *heout16 = HE16[lb ^ 1];
            uint16_t* hmin16 = HM16[lb], *hmout16 = HM16[lb ^ 1];

            gemm16(XE16, 512, SPIH, 512, hein16, 1024, SPHH, 512, bspi,
                   nullptr, 0, nullptr, 0, nullptr, nullptr, hein32, part, nullptr, 0,
                   heout32, heout16, nullptr, nullptr, 0, BB, H4, 2, dsm, blockIdx.x, NBLK);
            gsync(++ph);

            if (blockIdx.x < 160) {
                gemm16(heout16, 1024, MDIH, 512, hmin16, 1024, MDHH, 512, bmdi,
                       nullptr, 0, nullptr, 0, nullptr, nullptr, hmin32, nullptr, nullptr, 0,
                       hmout32, hmout16, mid2 + (size_t)l * HH, MID216 + (size_t)l * HH, LEN * HH,
                       BB, H4, 2, dsm, blockIdx.x, 160);
            } else if (l < LEN - 1) {
                gemm16(heout16, 1024, WE16, K2H, nullptr, 0, nullptr, 0, nullptr,
                       wiseq + (size_t)(l + 1) * HH, LEN * HH, wtwho, K2H,
                       nullptr, nullptr, nullptr, nullptr, nullptr, 0,
                       nullptr, TU16, nullptr, nullptr, 0, BB, HH, 1, dsm, blockIdx.x - 160, 136);
            }
            gsync(++ph);

            if (l < LEN - 1) {
                gemm16(TU16, 512, VD16, 512, nullptr, 0, nullptr, 0, p.Vd_b,
                       nullptr, 0, nullptr, 0, nullptr, nullptr, nullptr, nullptr,
                       p.inp + (size_t)(l + 1) * 512, LEN * 512,
                       part, XE16, nullptr, nullptr, 0, BB, HH, 3, dsm, blockIdx.x, NBLK);
                gsync(++ph);
            }
        }

        gemm16(MID216, 512, WX16, 512, nullptr, 0, nullptr, 0, p.Wx_b,
               nullptr, 0, nullptr, 0, nullptr, nullptr, nullptr, nullptr, nullptr, 0,
               ybuf, nullptr, nullptr, nullptr, 0, BB * LEN, HH, 0, dsm, blockIdx.x, NBLK);
        gsync(++ph);

        if (blockIdx.x < BB) {
            const int b = blockIdx.x;
            for (int l = wid; l < LEN; l += 8) {
                const float* yr = ybuf + ((size_t)b * LEN + l) * HH;
                float pv = 0.f;
                for (int h = lane; h < HH; h += 32)
                    pv += tanhf(wtwho[(size_t)b * K2H + 512 + h] + yr[h]) * p.V_w[h];
#pragma unroll
                for (int o = 16; o; o >>= 1) pv += __shfl_xor_sync(0xffffffffu, pv, o);
                if (lane == 0) ssc[l] = pv + p.V_b[0];
            }
            __syncthreads();
            float a0 = 0.f, a1 = 0.f;
            for (int l = 0; l < LEN; l++) {
                const float s = ssc[l];
                const float* mr = mid2 + ((size_t)b * LEN + l) * HH;
                a0 += s * mr[tid]; a1 += s * mr[tid + 256];
            }
            DEC16[(size_t)b * 512 + tid]       = __half_as_ushort(__float2half_rn(a0));
            DEC16[(size_t)b * 512 + tid + 256] = __half_as_ushort(__float2half_rn(a1));
        }
        gsync(++ph);
    }
}

__global__ __launch_bounds__(256) void prep_k(
    const float* bihsp, const float* bhhsp, const float* bihtg, const float* bhhtg,
    const float* bihmid, const float* bhhmid, const float* wihtg,
    const float* wtw, const float* whw,
    const float* wisp, const float* whsp, const float* whtg,
    const float* wimd, const float* whmd,
    const float* wiw, const float* wew, const float* vdw, const float* wxw,
    const float* inp)
{
    const int nt = gridDim.x * 256;
    const int gid = blockIdx.x * 256 + threadIdx.x;
    __half* WI16 = (__half*)(g_buf + O_WI16);
    __half* WE16 = (__half*)(g_buf + O_WE16);
    __half* VD16 = (__half*)(g_buf + O_VD16);
    __half* WX16 = (__half*)(g_buf + O_WX16);
    __half* WTWH16 = (__half*)(g_buf + O_WTWH16);
    __half* SPIH = (__half*)(g_buf + O_SPIH);
    __half* SPHH = (__half*)(g_buf + O_SPHH);
    __half* TGX = (__half*)(g_buf + O_TGX);
    __half* TGHH = (__half*)(g_buf + O_TGHH);
    __half* MDIH = (__half*)(g_buf + O_MDIH);
    __half* MDHH = (__half*)(g_buf + O_MDHH);
    __half* INP16 = (__half*)(g_buf + O_INP16);

    for (int i = gid; i < 512*512; i += nt) {
        WI16[i] = __float2half_rn(wiw[i]);
        VD16[i] = __float2half_rn(vdw[i]);
        WX16[i] = __float2half_rn(wxw[i]);
    }
    for (int i = gid; i < 512*1024; i += nt) WE16[i] = __float2half_rn(wew[i]);
    for (int i = gid; i < 1024*1024; i += nt) {
        const int r = i >> 10, c = i & 1023;
        WTWH16[i] = __float2half_rn(r < 512 ? wtw[(size_t)r*1024 + c] : whw[(size_t)(r-512)*1024 + c]);
    }
    for (int i = gid; i < BB*LEN*512; i += nt) INP16[i] = __float2half_rn(inp[i]);
    for (int i = gid; i < H4*512; i += nt) {
        const int rp = i >> 9, kk = i & 511;
        const int h = rp >> 2, gg = rp & 3;
        const size_t src = (size_t)(gg * 512 + h);
        SPIH[i] = __float2half_rn(wisp[src*512 + kk]);
        SPHH[i] = __float2half_rn(whsp[src*512 + kk]);
        TGHH[i] = __float2half_rn(whtg[src*512 + kk]);
        MDIH[i] = __float2half_rn(wimd[src*512 + kk]);
        MDHH[i] = __float2half_rn(whmd[src*512 + kk]);
        TGX[i]  = __float2half_rn(wihtg[src*513 + 1 + kk]);
    }
    for (int i = gid; i < H4; i += nt) {
        const int h = i >> 2, gg = i & 3;
        const int s = gg * 512 + h;
        g_buf[O_BSPI + i]  = bihsp[s] + bhhsp[s];
        g_buf[O_BTGI + i]  = bihtg[s] + bhhtg[s];
        g_buf[O_BMDI + i]  = bihmid[s] + bhhmid[s];
        g_buf[O_WTGCI + i] = wihtg[(size_t)s * 513];
    }
}

__global__ __launch_bounds__(256) void init_k(const float* __restrict__ labp)
{
    const int i = blockIdx.x * 256 + threadIdx.x;
    if (i < NSUB) g_arr[i * 32] = 0u;
    if (i == NSUB) g_master = 0u;
    if (i == NSUB + 1) g_rel = 0u;
    if (i < BB * K2H) {
        g_buf[O_HT0 + i] = 0.f;
        ((uint16_t*)(g_buf + O_HT16A))[i] = 0;
    }
    if (i < BB * HH) ((uint16_t*)(g_buf + O_DEC16))[i] = 0;
    if (i < BB) g_buf[O_LAB + i] = labp[(size_t)i * LABW + STARTI];
}

extern "C" void kernel_launch(void* const* d_in, const int* in_sizes, int n_in,
                              void* d_out, int out_size)
{
    Params p;
    p.inp   = (const float*)d_in[0];
    p.Wi_b  = (const float*)d_in[15];
    p.Vd_b  = (const float*)d_in[19];
    p.Wx_b  = (const float*)d_in[21];
    p.V_w   = (const float*)d_in[23];
    p.V_b   = (const float*)d_in[24];
    p.reg_w = (const float*)d_in[25];
    p.reg_b = (const float*)d_in[26];
    p.out   = (float*)d_out;

    float* gb = nullptr;
    cudaGetSymbolAddress((void**)&gb, g_buf);
    p.gb = gb;

    cudaFuncSetAttribute(mega, cudaFuncAttributeMaxDynamicSharedMemorySize, SMEMB);

    prep_k<<<2048, 256>>>(
        (const float*)d_in[4], (const float*)d_in[5], (const float*)d_in[8],
        (const float*)d_in[9], (const float*)d_in[12], (const float*)d_in[13],
        (const float*)d_in[6], (const float*)d_in[17], (const float*)d_in[22],
        (const float*)d_in[2], (const float*)d_in[3], (const float*)d_in[7],
        (const float*)d_in[10], (const float*)d_in[11],
        (const float*)d_in[14], (const float*)d_in[16],
        (const float*)d_in[18], (const float*)d_in[20],
        (const float*)d_in[0]);
    init_k<<<(BB * K2H + 255) / 256, 256>>>((const float*)d_in[1]);
    mega<<<NBLK, NTHR, SMEMB>>>(p);
}

// round 16
// speedup vs baseline: 3.0707x; 1.1326x over previous
#include <cuda_runtime.h>
#include <cuda_fp16.h>
#include <math.h>
#include <stdint.h>

#define BB 256
#define HH 512
#define H4 2048
#define LEN 48
#define LOOKN 10
#define K2H 1024
#define STARTI 48
#define LABW 58
#define NBLK 296
#define NTHR 256
#define NSUB 8
#define SUBCNT 37
#define PADU 36
#define ABUFS (4*64*PADU)
#define SMEMB (2*ABUFS*4)

constexpr size_t O_WISEQ = 0;
constexpr size_t O_MID2  = O_WISEQ + (size_t)BB*LEN*HH;
constexpr size_t O_Y     = O_MID2  + (size_t)BB*LEN*HH;
constexpr size_t O_HT0   = O_Y     + (size_t)BB*LEN*HH;
constexpr size_t O_HT1   = O_HT0   + (size_t)BB*K2H;
constexpr size_t O_HE0   = O_HT1   + (size_t)BB*K2H;
constexpr size_t O_HE1   = O_HE0   + (size_t)BB*K2H;
constexpr size_t O_HM0   = O_HE1   + (size_t)BB*K2H;
constexpr size_t O_HM1   = O_HM0   + (size_t)BB*K2H;
constexpr size_t O_WTWHO = O_HM1   + (size_t)BB*K2H;
constexpr size_t O_LAB   = O_WTWHO + (size_t)BB*K2H;
constexpr size_t O_PART  = O_LAB   + 1024;
constexpr size_t O_BSPI  = O_PART  + (size_t)BB*16;
constexpr size_t O_BTGI  = O_BSPI  + H4;
constexpr size_t O_BMDI  = O_BTGI  + H4;
constexpr size_t O_WTGCI = O_BMDI  + H4;
constexpr size_t O_INP16 = O_WTGCI + H4;
constexpr size_t O_MID216= O_INP16 + (size_t)BB*LEN*256;
constexpr size_t O_DEC16 = O_MID216+ (size_t)BB*LEN*256;
constexpr size_t O_XE16  = O_DEC16 + (size_t)BB*256;
constexpr size_t O_TU16  = O_XE16  + (size_t)BB*256;
constexpr size_t O_HT16A = O_TU16  + (size_t)BB*256;
constexpr size_t O_HT16B = O_HT16A + (size_t)BB*512;
constexpr size_t O_HE16A = O_HT16B + (size_t)BB*512;
constexpr size_t O_HE16B = O_HE16A + (size_t)BB*512;
constexpr size_t O_HM16A = O_HE16B + (size_t)BB*512;
constexpr size_t O_HM16B = O_HM16A + (size_t)BB*512;
constexpr size_t O_WI16  = O_HM16B + (size_t)BB*512;
constexpr size_t O_WE16  = O_WI16  + (size_t)512*256;
constexpr size_t O_VD16  = O_WE16  + (size_t)512*512;
constexpr size_t O_WX16  = O_VD16  + (size_t)512*256;
constexpr size_t O_WTWH16= O_WX16  + (size_t)512*256;
constexpr size_t O_SPIH  = O_WTWH16+ (size_t)1024*512;
constexpr size_t O_SPHH  = O_SPIH  + (size_t)H4*256;
constexpr size_t O_TGX   = O_SPHH  + (size_t)H4*256;
constexpr size_t O_TGHH  = O_TGX   + (size_t)H4*256;
constexpr size_t O_MDIH  = O_TGHH  + (size_t)H4*256;
constexpr size_t O_MDHH  = O_MDIH  + (size_t)H4*256;
constexpr size_t O_PARTP = O_MDHH  + (size_t)H4*256;     // fp32 partial [BB][H4]
constexpr size_t G_TOTAL = O_PARTP + (size_t)BB*H4;

__device__ float g_buf[G_TOTAL];
__device__ __align__(128) unsigned g_arr[NSUB * 32];
__device__ unsigned g_master;
__device__ unsigned g_rel;
__device__ __align__(128) unsigned g_flag[4 * 32];

__device__ __forceinline__ void gsync(unsigned ph)
{
    __syncthreads();
    if (threadIdx.x == 0) {
        __threadfence();
        const unsigned sub = blockIdx.x & (NSUB - 1);
        const unsigned v = atomicAdd(&g_arr[sub * 32], 1u) + 1u;
        if (v == ph * (unsigned)SUBCNT) {
            const unsigned m = atomicAdd(&g_master, 1u) + 1u;
            if (m == ph * (unsigned)NSUB) atomicExch(&g_rel, ph);
        }
        while (*(volatile unsigned*)&g_rel < ph) { __nanosleep(32); }
        __threadfence();
    }
    __syncthreads();
}

__device__ __forceinline__ uint32_t s2u(const void* p)
{ uint32_t a; asm("{ .reg .u64 t; cvta.to.shared.u64 t, %1; cvt.u32.u64 %0, t; }" : "=r"(a) : "l"(p)); return a; }

__device__ __forceinline__ void mma_f16(float* d,
    uint32_t a0, uint32_t a1, uint32_t a2, uint32_t a3, uint32_t b0, uint32_t b1)
{
    asm volatile(
        "mma.sync.aligned.m16n8k16.row.col.f32.f16.f16.f32 "
        "{%0,%1,%2,%3},{%4,%5,%6,%7},{%8,%9},{%0,%1,%2,%3};"
        : "+f"(d[0]), "+f"(d[1]), "+f"(d[2]), "+f"(d[3])
        : "r"(a0), "r"(a1), "r"(a2), "r"(a3), "r"(b0), "r"(b1));
}

struct Params {
    const float *inp;
    const float *Wi_b, *Vd_b, *Wx_b, *V_w, *V_b, *reg_w, *reg_b;
    float* out; float* gb;
};

__device__ __forceinline__ void cpAB(uint32_t sb, int buf, int srow, int sq,
    const uint16_t* Ap, int Alda, int m0,
    const uint16_t* Wp, int Wld, int n0, int ko)
{
    const uint16_t* ar = Ap + (size_t)(m0 + srow) * Alda + ko + sq * 16;
    const uint16_t* wr = Wp + (size_t)(n0 + srow) * Wld + ko + sq * 16;
    const uint32_t da = sb + ((buf * 64 + srow) * PADU + sq * 8) * 4;
    const uint32_t db = da + ABUFS * 4;
    asm volatile(
        "cp.async.ca.shared.global [%0],[%4],16;\n\t"
        "cp.async.ca.shared.global [%1],[%5],16;\n\t"
        "cp.async.ca.shared.global [%2],[%6],16;\n\t"
        "cp.async.ca.shared.global [%3],[%7],16;\n\t"
        "cp.async.commit_group;"
        :: "r"(da), "r"(da+16), "r"(db), "r"(db+16),
           "l"(ar), "l"(ar+8), "l"(wr), "l"(wr+8) : "memory");
}

// modes: 0 fp32 store(+bias); 1 tanh->fp16(+add1+add2); 2 fused LSTM(+opt bias/add1/r1);
//        3 exp: xe16 + partial sums
__device__ void gemm16(
    const uint16_t* A1, int lda1, const uint16_t* W1, int K1,
    const uint16_t* A2, int lda2, const uint16_t* W2, int K2,
    const float* bias, const float* add1, int ld1, const float* add2, int ld2,
    const float* r1u, const float* r1v,
    const float* cin, const float* invp,
    const float* xsrc, int xld,
    float* out32, uint16_t* out16,
    float* hout32, uint16_t* hout16, int hstride,
    int M, int N, int mode,
    uint32_t* dsm, int vbid, int vgrid,
    unsigned* sigf, const unsigned* waitf, unsigned wtarget)
{
    const int tid = threadIdx.x, wid = tid >> 5, lane = tid & 31;
    const int g = lane >> 2, c4 = lane & 3;
    const int wm = (wid >> 1) << 4, wn = (wid & 1) << 5;
    const int srow = tid >> 2, sq = tid & 3;
    const int NC = (K1 + K2) >> 6, k1c = K1 >> 6;
    const int nct = N >> 6, ntiles = (M >> 6) * nct;
    const uint32_t sb = s2u(dsm);
    const uint32_t* Bb = dsm + ABUFS;

    for (int t = vbid; t < ntiles; t += vgrid) {
        const int m0 = (t / nct) << 6, n0 = (t % nct) << 6;

        if (waitf) {
            if (tid == 0) {
                while (*(volatile const unsigned*)&waitf[(m0 >> 6) * 32] < wtarget)
                    __nanosleep(32);
            }
            __syncthreads();
            __threadfence();
        }

        float sc2[2] = {1.f, 1.f};
        if (invp) {
#pragma unroll
            for (int r = 0; r < 2; r++) {
                const int row = m0 + wm + (r << 3) + g;
                float s = 0.f;
#pragma unroll
                for (int q = 0; q < 16; q++) s += invp[row * 16 + q];
                sc2[r] = 1.f / s;
            }
        }

        float acc[4][4];
#pragma unroll
        for (int j = 0; j < 4; j++)
#pragma unroll
            for (int q = 0; q < 4; q++) acc[j][q] = 0.f;

#pragma unroll
        for (int s = 0; s < 3; s++) {
            if (s < NC) {
                const int kb = s << 6;
                if (kb < K1) cpAB(sb, s, srow, sq, A1, lda1, m0, W1, K1, n0, kb);
                else         cpAB(sb, s, srow, sq, A2, lda2, m0, W2, K2, n0, kb - K1);
            }
        }

        for (int c = 0; c < NC; c++) {
            const int rem = NC - 1 - c;                 // groups still outstanding beyond c
            const int pend = rem < 2 ? rem : 2;
            if (pend == 2)      asm volatile("cp.async.wait_group 2;" ::: "memory");
            else if (pend == 1) asm volatile("cp.async.wait_group 1;" ::: "memory");
            else                asm volatile("cp.async.wait_group 0;" ::: "memory");
            __syncthreads();
            const int cn = c + 3;
            if (cn < NC) {
                const int kb = cn << 6;
                if (kb < K1) cpAB(sb, cn & 3, srow, sq, A1, lda1, m0, W1, K1, n0, kb);
                else         cpAB(sb, cn & 3, srow, sq, A2, lda2, m0, W2, K2, n0, kb - K1);
            }
            const int b = c & 3;
#pragma unroll
            for (int ks = 0; ks < 4; ks++) {
                uint32_t af[4], bf[4][2];
                {
                    const uint32_t* ab  = dsm + (b * 64 + wm + g) * PADU + ks * 8;
                    const uint32_t* ab8 = dsm + (b * 64 + wm + g + 8) * PADU + ks * 8;
                    af[0] = ab[c4];   af[1] = ab8[c4];
                    af[2] = ab[c4+4]; af[3] = ab8[c4+4];
                }
#pragma unroll
                for (int nf = 0; nf < 4; nf++) {
                    const int r = wn + (nf << 3) + g;
                    const uint32_t* bb = Bb + (b * 64 + r) * PADU + ks * 8;
                    bf[nf][0] = bb[c4]; bf[nf][1] = bb[c4 + 4];
                }
#pragma unroll
                for (int nf = 0; nf < 4; nf++)
                    mma_f16(acc[nf], af[0], af[1], af[2], af[3], bf[nf][0], bf[nf][1]);
            }
            if (invp && c == k1c - 1) {
#pragma unroll
                for (int nf = 0; nf < 4; nf++) {
                    acc[nf][0] *= sc2[0]; acc[nf][1] *= sc2[0];
                    acc[nf][2] *= sc2[1]; acc[nf][3] *= sc2[1];
                }
            }
        }

        const int mA = m0 + wm + g, mB = mA + 8;
        const int nb0 = n0 + wn;
        if (mode == 0) {
#pragma unroll
            for (int nf = 0; nf < 4; nf++) {
                const int nc = nb0 + (nf << 3) + (c4 << 1);
                float x0 = acc[nf][0], x1 = acc[nf][1];
                float x2 = acc[nf][2], x3 = acc[nf][3];
                if (bias) { x0 += bias[nc]; x1 += bias[nc+1]; x2 += bias[nc]; x3 += bias[nc+1]; }
                *(float2*)(out32 + (size_t)mA * N + nc) = make_float2(x0, x1);
                *(float2*)(out32 + (size_t)mB * N + nc) = make_float2(x2, x3);
            }
        } else if (mode == 1) {
#pragma unroll
            for (int nf = 0; nf < 4; nf++) {
                const int nc = nb0 + (nf << 3) + (c4 << 1);
                float x0 = acc[nf][0], x1 = acc[nf][1];
                float x2 = acc[nf][2], x3 = acc[nf][3];
                x0 += add1[(size_t)mA*ld1+nc]; x1 += add1[(size_t)mA*ld1+nc+1];
                x2 += add1[(size_t)mB*ld1+nc]; x3 += add1[(size_t)mB*ld1+nc+1];
                x0 += add2[(size_t)mA*ld2+nc]; x1 += add2[(size_t)mA*ld2+nc+1];
                x2 += add2[(size_t)mB*ld2+nc]; x3 += add2[(size_t)mB*ld2+nc+1];
                __half2 hA = __floats2half2_rn(tanhf(x0), tanhf(x1));
                __half2 hB = __floats2half2_rn(tanhf(x2), tanhf(x3));
                *(uint32_t*)(out16 + (size_t)mA * N + nc) = *(uint32_t*)&hA;
                *(uint32_t*)(out16 + (size_t)mB * N + nc) = *(uint32_t*)&hB;
            }
        } else if (mode == 3) {
            float sA = 0.f, sB = 0.f;
#pragma unroll
            for (int nf = 0; nf < 4; nf++) {
                const int nc = nb0 + (nf << 3) + (c4 << 1);
                float e0 = expf(acc[nf][0] + bias[nc]);
                float e1 = expf(acc[nf][1] + bias[nc+1]);
                float e2 = expf(acc[nf][2] + bias[nc]);
                float e3 = expf(acc[nf][3] + bias[nc+1]);
                sA += e0 + e1; sB += e2 + e3;
                float2 xa = *(const float2*)(xsrc + (size_t)mA * xld + nc);
                float2 xb = *(const float2*)(xsrc + (size_t)mB * xld + nc);
                __half2 hA = __floats2half2_rn(xa.x * e0, xa.y * e1);
                __half2 hB = __floats2half2_rn(xb.x * e2, xb.y * e3);
                *(uint32_t*)(out16 + (size_t)mA * 512 + nc) = *(uint32_t*)&hA;
                *(uint32_t*)(out16 + (size_t)mB * 512 + nc) = *(uint32_t*)&hB;
            }
            sA += __shfl_xor_sync(0xffffffffu, sA, 1);
            sA += __shfl_xor_sync(0xffffffffu, sA, 2);
            sB += __shfl_xor_sync(0xffffffffu, sB, 1);
            sB += __shfl_xor_sync(0xffffffffu, sB, 2);
            if (c4 == 0) {
                out32[mA * 16 + (nb0 >> 5)] = sA;
                out32[mB * 16 + (nb0 >> 5)] = sB;
            }
        } else {
            const float ra = r1u ? r1u[mA] : 0.f, rb = r1u ? r1u[mB] : 0.f;
#pragma unroll
            for (int nf = 0; nf < 4; nf++) {
                const int nc = nb0 + (nf << 3) + (c4 << 1);
                float v00 = acc[nf][0], v01 = acc[nf][1];
                float v10 = acc[nf][2], v11 = acc[nf][3];
                if (bias) { v00 += bias[nc]; v01 += bias[nc+1]; v10 += bias[nc]; v11 += bias[nc+1]; }
                if (add1) {
                    v00 += add1[(size_t)mA*ld1+nc]; v01 += add1[(size_t)mA*ld1+nc+1];
                    v10 += add1[(size_t)mB*ld1+nc]; v11 += add1[(size_t)mB*ld1+nc+1];
                }
                if (r1u) {
                    v00 += ra * r1v[nc]; v01 += ra * r1v[nc+1];
                    v10 += rb * r1v[nc]; v11 += rb * r1v[nc+1];
                }
                const float t00 = __shfl_xor_sync(0xffffffffu, v00, 1);
                const float t01 = __shfl_xor_sync(0xffffffffu, v01, 1);
                const float t10 = __shfl_xor_sync(0xffffffffu, v10, 1);
                const float t11 = __shfl_xor_sync(0xffffffffu, v11, 1);
                int m; float fi, ff, fg, fo;
                if ((c4 & 1) == 0) { m = mA; fi = v00; ff = v01; fg = t00; fo = t01; }
                else               { m = mB; fi = t10; ff = t11; fg = v10; fo = v11; }
                const int h = ((nb0 + (nf << 3)) >> 2) + (c4 >> 1);
                const float cold = cin[(size_t)m * 1024 + 512 + h];
                const float si = 1.f / (1.f + expf(-fi));
                const float sf = 1.f / (1.f + expf(-ff));
                const float so = 1.f / (1.f + expf(-fo));
                const float c2 = sf * cold + si * tanhf(fg);
                const float hn = so * tanhf(c2);
                out32[(size_t)m * 1024 + h] = hn;
                out32[(size_t)m * 1024 + 512 + h] = c2;
                out16[(size_t)m * 1024 + h] = __half_as_ushort(__float2half_rn(hn));
                out16[(size_t)m * 1024 + 512 + h] = __half_as_ushort(__float2half_rn(c2));
                if (hout32) {
                    hout32[(size_t)m * hstride + h] = hn;
                    hout16[(size_t)m * hstride + h] = __half_as_ushort(__float2half_rn(hn));
                }
            }
        }
        if (sigf) {
            __threadfence();
            __syncthreads();
            if (tid == 0) atomicAdd(&sigf[(m0 >> 6) * 32], 1u);
        } else {
            __syncthreads();
        }
    }
}

__global__ __launch_bounds__(NTHR, 2) void mega(Params p)
{
    extern __shared__ uint32_t dsm[];
    __shared__ float ssc[LEN];
    const int tid = threadIdx.x, wid = tid >> 5, lane = tid & 31;

    float* gb = p.gb;
    float* wiseq = gb + O_WISEQ;  float* mid2 = gb + O_MID2;  float* ybuf = gb + O_Y;
    float* ht0 = gb + O_HT0;  float* ht1 = gb + O_HT1;
    float* he0 = gb + O_HE0;  float* hm0 = gb + O_HM0;
    float* he1 = gb + O_HE1;  float* hm1 = gb + O_HM1;
    float* wtwho = gb + O_WTWHO;  float* lab = gb + O_LAB;  float* part = gb + O_PART;
    float* Pbuf = gb + O_PARTP;
    float* bspi = gb + O_BSPI;  float* btgi = gb + O_BTGI;
    float* bmdi = gb + O_BMDI;  float* wtgci = gb + O_WTGCI;
    uint16_t* INP16 = (uint16_t*)(gb + O_INP16);
    uint16_t* MID216 = (uint16_t*)(gb + O_MID216);
    uint16_t* DEC16 = (uint16_t*)(gb + O_DEC16);
    uint16_t* XE16 = (uint16_t*)(gb + O_XE16);
    uint16_t* TU16 = (uint16_t*)(gb + O_TU16);
    uint16_t* HT16[2] = {(uint16_t*)(gb + O_HT16A), (uint16_t*)(gb + O_HT16B)};
    uint16_t* HE16[2] = {(uint16_t*)(gb + O_HE16A), (uint16_t*)(gb + O_HE16B)};
    uint16_t* HM16[2] = {(uint16_t*)(gb + O_HM16A), (uint16_t*)(gb + O_HM16B)};
    const uint16_t* WI16 = (const uint16_t*)(gb + O_WI16);
    const uint16_t* WE16 = (const uint16_t*)(gb + O_WE16);
    const uint16_t* VD16 = (const uint16_t*)(gb + O_VD16);
    const uint16_t* WX16 = (const uint16_t*)(gb + O_WX16);
    const uint16_t* WTWH16 = (const uint16_t*)(gb + O_WTWH16);
    const uint16_t* SPIH = (const uint16_t*)(gb + O_SPIH);
    const uint16_t* SPHH = (const uint16_t*)(gb + O_SPHH);
    const uint16_t* TGX = (const uint16_t*)(gb + O_TGX);
    const uint16_t* TGHH = (const uint16_t*)(gb + O_TGHH);
    const uint16_t* MDIH = (const uint16_t*)(gb + O_MDIH);
    const uint16_t* MDHH = (const uint16_t*)(gb + O_MDHH);
    unsigned* flagp = g_flag;

    unsigned ph = 0;
    unsigned fstep = 0;

    gemm16(INP16, 512, WI16, 512, nullptr, 0, nullptr, 0, p.Wi_b,
           nullptr, 0, nullptr, 0, nullptr, nullptr, nullptr, nullptr, nullptr, 0,
           wiseq, nullptr, nullptr, nullptr, 0, BB*LEN, HH, 0, dsm, blockIdx.x, NBLK,
           nullptr, nullptr, 0);
    gsync(++ph);

    for (int k = 0; k < LOOKN; k++) {
        const int kb = k & 1;
        float* htin32  = kb ? ht1 : ht0;
        float* htout32 = kb ? ht0 : ht1;
        uint16_t* htin16  = HT16[kb];
        uint16_t* htout16 = HT16[kb ^ 1];

        // tg gates (fused LSTM)
        gemm16(DEC16, 512, TGX, 512, htin16, 1024, TGHH, 512, btgi,
               nullptr, 0, nullptr, 0, lab, wtgci, htin32, nullptr, nullptr, 0,
               htout32, htout16, nullptr, nullptr, 0, BB, H4, 2, dsm, blockIdx.x, NBLK,
               nullptr, nullptr, 0);
        gsync(++ph);

        // wtwh || target || zero states + P0 = bias
        if (blockIdx.x < 64) {
            gemm16(htout16, 1024, WTWH16, K2H, nullptr, 0, nullptr, 0, nullptr,
                   nullptr, 0, nullptr, 0, nullptr, nullptr, nullptr, nullptr, nullptr, 0,
                   wtwho, nullptr, nullptr, nullptr, 0, BB, K2H, 0, dsm, blockIdx.x, 64,
                   nullptr, nullptr, 0);
        } else if (blockIdx.x == 64) {
            for (int r = wid; r < BB; r += 8) {
                float s = 0.f;
                for (int h = lane; h < HH; h += 32) s += htout32[(size_t)r * K2H + h] * p.reg_w[h];
#pragma unroll
                for (int o = 16; o; o >>= 1) s += __shfl_xor_sync(0xffffffffu, s, o);
                if (lane == 0) { const float tv = s + p.reg_b[0]; p.out[r * LOOKN + k] = tv; lab[r] = tv; }
            }
        } else {
            const int base = (blockIdx.x - 65) * NTHR + tid;
            for (int i = base; i < BB * K2H; i += (NBLK - 65) * NTHR) {
                he0[i] = 0.f; hm0[i] = 0.f;
                ((uint32_t*)HE16[0])[i >> 1] = 0u; ((uint32_t*)HM16[0])[i >> 1] = 0u;
            }
            for (int i = base; i < BB * H4; i += (NBLK - 65) * NTHR)
                Pbuf[i] = bspi[i & (H4 - 1)];
        }
        gsync(++ph);

        // tu(0) -> sc(0) flag-chained (P(0) already = bias since he(0)=0)
        fstep++;
        if (blockIdx.x >= 128 && blockIdx.x < 160) {
            gemm16(HE16[0], 1024, WE16, K2H, nullptr, 0, nullptr, 0, nullptr,
                   wiseq, LEN * HH, wtwho, K2H, nullptr, nullptr, nullptr, nullptr, nullptr, 0,
                   nullptr, TU16, nullptr, nullptr, 0, BB, HH, 1, dsm, blockIdx.x - 128, 32,
                   flagp, nullptr, 0);
        } else if (blockIdx.x >= 160 && blockIdx.x < 192) {
            gemm16(TU16, 512, VD16, 512, nullptr, 0, nullptr, 0, p.Vd_b,
                   nullptr, 0, nullptr, 0, nullptr, nullptr, nullptr, nullptr,
                   p.inp, LEN * 512,
                   part, XE16, nullptr, nullptr, 0, BB, HH, 3, dsm, blockIdx.x - 160, 32,
                   nullptr, flagp, 8u * fstep);
        }
        gsync(++ph);

        for (int l = 0; l < LEN; l++) {
            const int lb = l & 1;
            float* hein32  = lb ? he1 : he0;
            float* heout32 = lb ? he0 : he1;
            float* hmin32  = lb ? hm1 : hm0;
            float* hmout32 = lb ? hm0 : hm1;
            uint16_t* hein16 = HE16[lb], *heout16 = HE16[lb ^ 1];
            uint16_t* hmin16 = HM16[lb], *hmout16 = HM16[lb ^ 1];
            (void)hein16;

            // Phase A: sp_xe(l) = inv*(XE@SPIH) + P, fused LSTM
            gemm16(XE16, 512, SPIH, 512, nullptr, 0, nullptr, 0,
                   nullptr, Pbuf, H4, nullptr, 0,
                   nullptr, nullptr, hein32, part, nullptr, 0,
                   heout32, heout16, nullptr, nullptr, 0, BB, H4, 2, dsm, blockIdx.x, NBLK,
                   nullptr, nullptr, 0);
            gsync(++ph);

            // Phase B: mid(l) || tu(l+1)->sc(l+1) || sp_hh(l+1)->P
            if (l < LEN - 1) fstep++;
            if (blockIdx.x < 128) {
                gemm16(heout16, 1024, MDIH, 512, hmin16, 1024, MDHH, 512, bmdi,
                       nullptr, 0, nullptr, 0, nullptr, nullptr, hmin32, nullptr, nullptr, 0,
                       hmout32, hmout16, mid2 + (size_t)l * HH, MID216 + (size_t)l * HH, LEN * HH,
                       BB, H4, 2, dsm, blockIdx.x, 128, nullptr, nullptr, 0);
            } else if (l < LEN - 1) {
                if (blockIdx.x < 160) {
                    gemm16(heout16, 1024, WE16, K2H, nullptr, 0, nullptr, 0, nullptr,
                           wiseq + (size_t)(l + 1) * HH, LEN * HH, wtwho, K2H,
                           nullptr, nullptr, nullptr, nullptr, nullptr, 0,
                           nullptr, TU16, nullptr, nullptr, 0, BB, HH, 1, dsm, blockIdx.x - 128, 32,
                           flagp, nullptr, 0);
                } else if (blockIdx.x < 192) {
                    gemm16(TU16, 512, VD16, 512, nullptr, 0, nullptr, 0, p.Vd_b,
                           nullptr, 0, nullptr, 0, nullptr, nullptr, nullptr, nullptr,
                           p.inp + (size_t)(l + 1) * 512, LEN * 512,
                           part, XE16, nullptr, nullptr, 0, BB, HH, 3, dsm, blockIdx.x - 160, 32,
                           nullptr, flagp, 8u * fstep);
                } else {
                    gemm16(heout16, 1024, SPHH, 512, nullptr, 0, nullptr, 0, bspi,
                           nullptr, 0, nullptr, 0, nullptr, nullptr, nullptr, nullptr, nullptr, 0,
                           Pbuf, nullptr, nullptr, nullptr, 0, BB, H4, 0, dsm, blockIdx.x - 192, 104,
                           nullptr, nullptr, 0);
                }
            }
            gsync(++ph);
        }

        gemm16(MID216, 512, WX16, 512, nullptr, 0, nullptr, 0, p.Wx_b,
               nullptr, 0, nullptr, 0, nullptr, nullptr, nullptr, nullptr, nullptr, 0,
               ybuf, nullptr, nullptr, nullptr, 0, BB * LEN, HH, 0, dsm, blockIdx.x, NBLK,
               nullptr, nullptr, 0);
        gsync(++ph);

        if (blockIdx.x < BB) {
            const int b = blockIdx.x;
            for (int l = wid; l < LEN; l += 8) {
                const float* yr = ybuf + ((size_t)b * LEN + l) * HH;
                float pv = 0.f;
                for (int h = lane; h < HH; h += 32)
                    pv += tanhf(wtwho[(size_t)b * K2H + 512 + h] + yr[h]) * p.V_w[h];
#pragma unroll
                for (int o = 16; o; o >>= 1) pv += __shfl_xor_sync(0xffffffffu, pv, o);
                if (lane == 0) ssc[l] = pv + p.V_b[0];
            }
            __syncthreads();
            float a0 = 0.f, a1 = 0.f;
            for (int l = 0; l < LEN; l++) {
                const float s = ssc[l];
                const float* mr = mid2 + ((size_t)b * LEN + l) * HH;
                a0 += s * mr[tid]; a1 += s * mr[tid + 256];
            }
            DEC16[(size_t)b * 512 + tid]       = __half_as_ushort(__float2half_rn(a0));
            DEC16[(size_t)b * 512 + tid + 256] = __half_as_ushort(__float2half_rn(a1));
        }
        gsync(++ph);
    }
}

__global__ __launch_bounds__(256) void prep_k(
    const float* bihsp, const float* bhhsp, const float* bihtg, const float* bhhtg,
    const float* bihmid, const float* bhhmid, const float* wihtg,
    const float* wtw, const float* whw,
    const float* wisp, const float* whsp, const float* whtg,
    const float* wimd, const float* whmd,
    const float* wiw, const float* wew, const float* vdw, const float* wxw,
    const float* inp)
{
    const int nt = gridDim.x * 256;
    const int gid = blockIdx.x * 256 + threadIdx.x;
    __half* WI16 = (__half*)(g_buf + O_WI16);
    __half* WE16 = (__half*)(g_buf + O_WE16);
    __half* VD16 = (__half*)(g_buf + O_VD16);
    __half* WX16 = (__half*)(g_buf + O_WX16);
    __half* WTWH16 = (__half*)(g_buf + O_WTWH16);
    __half* SPIH = (__half*)(g_buf + O_SPIH);
    __half* SPHH = (__half*)(g_buf + O_SPHH);
    __half* TGX = (__half*)(g_buf + O_TGX);
    __half* TGHH = (__half*)(g_buf + O_TGHH);
    __half* MDIH = (__half*)(g_buf + O_MDIH);
    __half* MDHH = (__half*)(g_buf + O_MDHH);
    __half* INP16 = (__half*)(g_buf + O_INP16);

    for (int i = gid; i < 512*512; i += nt) {
        WI16[i] = __float2half_rn(wiw[i]);
        VD16[i] = __float2half_rn(vdw[i]);
        WX16[i] = __float2half_rn(wxw[i]);
    }
    for (int i = gid; i < 512*1024; i += nt) WE16[i] = __float2half_rn(wew[i]);
    for (int i = gid; i < 1024*1024; i += nt) {
        const int r = i >> 10, c = i & 1023;
        WTWH16[i] = __float2half_rn(r < 512 ? wtw[(size_t)r*1024 + c] : whw[(size_t)(r-512)*1024 + c]);
    }
    for (int i = gid; i < BB*LEN*512; i += nt) INP16[i] = __float2half_rn(inp[i]);
    for (int i = gid; i < H4*512; i += nt) {
        const int rp = i >> 9, kk = i & 511;
        const int h = rp >> 2, gg = rp & 3;
        const size_t src = (size_t)(gg * 512 + h);
        SPIH[i] = __float2half_rn(wisp[src*512 + kk]);
        SPHH[i] = __float2half_rn(whsp[src*512 + kk]);
        TGHH[i] = __float2half_rn(whtg[src*512 + kk]);
        MDIH[i] = __float2half_rn(wimd[src*512 + kk]);
        MDHH[i] = __float2half_rn(whmd[src*512 + kk]);
        TGX[i]  = __float2half_rn(wihtg[src*513 + 1 + kk]);
    }
    for (int i = gid; i < H4; i += nt) {
        const int h = i >> 2, gg = i & 3;
        const int s = gg * 512 + h;
        g_buf[O_BSPI + i]  = bihsp[s] + bhhsp[s];
        g_buf[O_BTGI + i]  = bihtg[s] + bhhtg[s];
        g_buf[O_BMDI + i]  = bihmid[s] + bhhmid[s];
        g_buf[O_WTGCI + i] = wihtg[(size_t)s * 513];
    }
}

__global__ __launch_bounds__(256) void init_k(const float* __restrict__ labp)
{
    const int i = blockIdx.x * 256 + threadIdx.x;
    if (i < NSUB) g_arr[i * 32] = 0u;
    if (i == NSUB) g_master = 0u;
    if (i == NSUB + 1) g_rel = 0u;
    if (i < 4) g_flag[i * 32] = 0u;
    if (i < BB * K2H) {
        g_buf[O_HT0 + i] = 0.f;
        ((uint16_t*)(g_buf + O_HT16A))[i] = 0;
    }
    if (i < BB * HH) ((uint16_t*)(g_buf + O_DEC16))[i] = 0;
    if (i < BB) g_buf[O_LAB + i] = labp[(size_t)i * LABW + STARTI];
}

extern "C" void kernel_launch(void* const* d_in, const int* in_sizes, int n_in,
                              void* d_out, int out_size)
{
    Params p;
    p.inp   = (const float*)d_in[0];
    p.Wi_b  = (const float*)d_in[15];
    p.Vd_b  = (const float*)d_in[19];
    p.Wx_b  = (const float*)d_in[21];
    p.V_w   = (const float*)d_in[23];
    p.V_b   = (const float*)d_in[24];
    p.reg_w = (const float*)d_in[25];
    p.reg_b = (const float*)d_in[26];
    p.out   = (float*)d_out;

    float* gb = nullptr;
    cudaGetSymbolAddress((void**)&gb, g_buf);
    p.gb = gb;

    cudaFuncSetAttribute(mega, cudaFuncAttributeMaxDynamicSharedMemorySize, SMEMB);

    prep_k<<<2048, 256>>>(
        (const float*)d_in[4], (const float*)d_in[5], (const float*)d_in[8],
        (const float*)d_in[9], (const float*)d_in[12], (const float*)d_in[13],
        (const float*)d_in[6], (const float*)d_in[17], (const float*)d_in[22],
        (const float*)d_in[2], (const float*)d_in[3], (const float*)d_in[7],
        (const float*)d_in[10], (const float*)d_in[11],
        (const float*)d_in[14], (const float*)d_in[16],
        (const float*)d_in[18], (const float*)d_in[20],
        (const float*)d_in[0]);
    init_k<<<(BB * K2H + 255) / 256, 256>>>((const float*)d_in[1]);
    mega<<<NBLK, NTHR, SMEMB>>>(p);
}